// round 1
// baseline (speedup 1.0000x reference)
#include <cuda_runtime.h>

#define NFFT    512
#define HOPSZ   128
#define BATCH   4
#define LSAMP   131072
#define TFRAMES 1025
#define KW      1023
#define NROWS   (BATCH * NFFT)   // 2048
#define TT      7
#define HPAD    2064             // >= 1025 + 2*511 + slack

// ------------- device scratch (static, no allocs) -------------
__device__ float2 g_H[BATCH * NFFT * TFRAMES];  // [b][n][t], full complex FFT bins
__device__ float2 g_K[NFFT * KW];               // [n][k]
__device__ double g_acc;

// ------------- reset accumulator -------------
__global__ void reset_kernel() { g_acc = 0.0; }

// ------------- K[n,k] = sum_q exp(+i 2pi n (q-3)/512) * alpha[q,k] -------------
__global__ void kcomp_kernel(const float* __restrict__ ar, const float* __restrict__ ai) {
    int idx = blockIdx.x * blockDim.x + threadIdx.x;
    if (idx >= NFFT * KW) return;
    int n = idx / KW;
    int k = idx - n * KW;
    float sr = 0.f, si = 0.f;
#pragma unroll
    for (int qi = 0; qi < 7; qi++) {
        float q   = (float)(qi - 3);
        float ang = 6.283185307179586f * (float)n * q * (1.0f / 512.0f);
        float s, c;
        sincosf(ang, &s, &c);
        float arv = ar[qi * KW + k];
        float aiv = ai[qi * KW + k];
        sr += c * arv - s * aiv;
        si += c * aiv + s * arv;
    }
    g_K[idx] = make_float2(sr, si);
}

// ------------- STFT: one frame per block, 512-pt DIF radix-2 FFT -------------
__global__ void stft_kernel(const float* __restrict__ wav, const float* __restrict__ win) {
    __shared__ float2 buf[NFFT];
    int t   = blockIdx.x;   // 0..1024
    int b   = blockIdx.y;   // 0..3
    int tid = threadIdx.x;  // 256 threads

    // load frame with reflect padding (pad = 256 each side), windowed
    for (int i = tid; i < NFFT; i += 256) {
        int p = t * HOPSZ + i - 256;
        if (p < 0) p = -p;
        if (p >= LSAMP) p = 2 * LSAMP - 2 - p;
        buf[i] = make_float2(wav[b * LSAMP + p] * win[i], 0.f);
    }
    __syncthreads();

    // DIF radix-2: natural input -> bit-reversed output
    for (int s = 256; s >= 1; s >>= 1) {
        int j   = tid & (s - 1);
        int blk = tid / s;
        int i0  = blk * (2 * s) + j;
        float ang = -3.14159265358979323846f * (float)j / (float)s;
        float sw, cw;
        sincosf(ang, &sw, &cw);
        float2 A = buf[i0];
        float2 B = buf[i0 + s];
        buf[i0] = make_float2(A.x + B.x, A.y + B.y);
        float dr = A.x - B.x, di = A.y - B.y;
        buf[i0 + s] = make_float2(dr * cw - di * sw, dr * sw + di * cw);
        __syncthreads();
    }

    // write out: bin n = bitrev9(i)
    for (int i = tid; i < NFFT; i += 256) {
        int n = (int)(__brev((unsigned)i) >> 23);
        g_H[(b * NFFT + n) * TFRAMES + t] = buf[i];
    }
}

// ------------- conv + |C|^2 accumulation: one (b,n) row per block -------------
__global__ void __launch_bounds__(160) conv_kernel() {
    __shared__ float2 sK[KW];
    __shared__ float  sHr[HPAD];
    __shared__ float  sHi[HPAD];

    int row = blockIdx.x;       // b*512 + n
    int tid = threadIdx.x;      // 160 threads (5 warps)

    const float2* __restrict__ Krow = &g_K[(row & (NFFT - 1)) * KW];
    for (int i = tid; i < KW; i += 160) sK[i] = Krow[i];
    for (int i = tid; i < HPAD; i += 160) { sHr[i] = 0.f; sHi[i] = 0.f; }
    __syncthreads();
    const float2* __restrict__ Hrow = &g_H[row * TFRAMES];
    for (int i = tid; i < TFRAMES; i += 160) {
        float2 h = Hrow[i];
        sHr[511 + i] = h.x;
        sHi[511 + i] = h.y;
    }
    __syncthreads();

    float lsum = 0.f;
    if (tid < 147) {                 // 147*7 = 1029 >= 1025 outputs
        int t0 = tid * TT;           // stride 7 (odd) -> conflict-free LDS
        float cr[TT], ci[TT], wr[TT], wi[TT];
#pragma unroll
        for (int j = 0; j < TT; j++) {
            cr[j] = 0.f; ci[j] = 0.f;
            wr[j] = sHr[t0 + j];     // padded index: t - 511 + tau + 511 = t0 + j + tau
            wi[j] = sHi[t0 + j];
        }
#pragma unroll 7
        for (int tau = 0; tau < KW; tau++) {
            float2 k = sK[tau];
#pragma unroll
            for (int j = 0; j < TT; j++) {
                cr[j] += k.x * wr[j];
                cr[j] -= k.y * wi[j];
                ci[j] += k.x * wi[j];
                ci[j] += k.y * wr[j];
            }
#pragma unroll
            for (int j = 0; j < TT - 1; j++) { wr[j] = wr[j + 1]; wi[j] = wi[j + 1]; }
            wr[TT - 1] = sHr[t0 + tau + TT];
            wi[TT - 1] = sHi[t0 + tau + TT];
        }
#pragma unroll
        for (int j = 0; j < TT; j++)
            if (t0 + j < TFRAMES)
                lsum += cr[j] * cr[j] + ci[j] * ci[j];
    }

    // block reduce -> double atomic
    __shared__ float warpsum[5];
#pragma unroll
    for (int off = 16; off > 0; off >>= 1)
        lsum += __shfl_down_sync(0xffffffff, lsum, off);
    if ((tid & 31) == 0) warpsum[tid >> 5] = lsum;
    __syncthreads();
    if (tid == 0) {
        float s = 0.f;
#pragma unroll
        for (int w = 0; w < 5; w++) s += warpsum[w];
        atomicAdd(&g_acc, (double)s);
    }
}

__global__ void finalize_kernel(float* out) {
    out[0] = (float)(g_acc / (double)(BATCH * TFRAMES));
}

extern "C" void kernel_launch(void* const* d_in, const int* in_sizes, int n_in,
                              void* d_out, int out_size) {
    const float* wav = (const float*)d_in[0];
    const float* win = (const float*)d_in[1];
    const float* ar  = (const float*)d_in[2];
    const float* ai  = (const float*)d_in[3];

    reset_kernel<<<1, 1>>>();
    kcomp_kernel<<<(NFFT * KW + 255) / 256, 256>>>(ar, ai);
    dim3 gs(TFRAMES, BATCH);
    stft_kernel<<<gs, 256>>>(wav, win);
    conv_kernel<<<NROWS, 160>>>();
    finalize_kernel<<<1, 1>>>((float*)d_out);
}

// round 2
// speedup vs baseline: 1.9582x; 1.9582x over previous
#include <cuda_runtime.h>

#define NFFT    512
#define HOPSZ   128
#define BATCH   4
#define LSAMP   131072
#define TFRAMES 1025
#define KW      1023
#define NROWS   (BATCH * NFFT)   // 2048
#define LFFT    2048

// ------------- device scratch (static, no allocs) -------------
__device__ float2 g_H[BATCH * NFFT * TFRAMES];  // [b][n][t], full complex FFT bins
__device__ float2 g_B[7 * LFFT];                // FFT'd alpha rows (bit-rev order)
__device__ float2 g_G[NFFT * LFFT];             // per-bin correlation spectrum (bit-rev)
__device__ float2 g_tw[1024];                   // tw[x] = exp(-i*pi*x/1024)
__device__ double g_acc;

__global__ void reset_kernel() { g_acc = 0.0; }

__global__ void twinit_kernel() {
    int i = blockIdx.x * blockDim.x + threadIdx.x;
    if (i < 1024) {
        float s, c;
        sincospif(-(float)i * (1.0f / 1024.0f), &s, &c);
        g_tw[i] = make_float2(c, s);
    }
}

// ---------------- in-shared radix-2 FFT helpers (2048 pts, 512 threads) ----------------
// Forward DIF: natural in -> bit-reversed out, twiddle sign -.
__device__ __forceinline__ void fft2048_fwd(float* re, float* im, const float2* tw, int tid) {
    int mult = 1;
    for (int s = 1024; s >= 1; s >>= 1, mult <<= 1) {
        __syncthreads();
#pragma unroll
        for (int r = 0; r < 2; r++) {
            int bf = tid + r * 512;
            int j  = bf & (s - 1);
            int i0 = ((bf - j) << 1) + j;
            float2 w = tw[j * mult];
            float ar = re[i0],     ai = im[i0];
            float br = re[i0 + s], bi = im[i0 + s];
            re[i0] = ar + br;  im[i0] = ai + bi;
            float dr = ar - br, di = ai - bi;
            re[i0 + s] = dr * w.x - di * w.y;
            im[i0 + s] = dr * w.y + di * w.x;
        }
    }
}

// Inverse DIT: bit-reversed in -> natural out, twiddle sign + (conj of table). No 1/L scale.
__device__ __forceinline__ void fft2048_inv(float* re, float* im, const float2* tw, int tid) {
    int mult = 1024;
    for (int s = 1; s <= 1024; s <<= 1, mult >>= 1) {
        __syncthreads();
#pragma unroll
        for (int r = 0; r < 2; r++) {
            int bf = tid + r * 512;
            int j  = bf & (s - 1);
            int i0 = ((bf - j) << 1) + j;
            float2 w = tw[j * mult];
            float br0 = re[i0 + s], bi0 = im[i0 + s];
            float br = br0 * w.x + bi0 * w.y;   // * conj(w)
            float bi = bi0 * w.x - br0 * w.y;
            float ar = re[i0], ai = im[i0];
            re[i0]     = ar + br;  im[i0]     = ai + bi;
            re[i0 + s] = ar - br;  im[i0 + s] = ai - bi;
        }
    }
}

// ---------------- FFT of the 7 conjugated alpha rows: B[q,f] = conj(DIF(conj(alpha_q))) ----------------
__global__ __launch_bounds__(512) void alphafft_kernel(const float* __restrict__ ar,
                                                       const float* __restrict__ ai) {
    __shared__ float sRe[LFFT], sIm[LFFT];
    __shared__ float2 sTw[1024];
    int q = blockIdx.x, tid = threadIdx.x;
    for (int i = tid; i < 1024; i += 512) sTw[i] = g_tw[i];
    for (int i = tid; i < LFFT; i += 512) {
        if (i < KW) { sRe[i] = ar[q * KW + i]; sIm[i] = -ai[q * KW + i]; }
        else        { sRe[i] = 0.f;            sIm[i] = 0.f; }
    }
    fft2048_fwd(sRe, sIm, sTw, tid);
    __syncthreads();
    for (int i = tid; i < LFFT; i += 512)
        g_B[q * LFFT + i] = make_float2(sRe[i], -sIm[i]);
}

// ---------------- G[n,f] = (1/L) * sum_q exp(+i*2pi*n*(q-3)/512) * B[q,f] ----------------
__global__ void gcomb_kernel() {
    __shared__ float2 ph[7];
    int n = blockIdx.x, tid = threadIdx.x;   // 256 threads
    if (tid < 7) {
        float ang = 2.0f * (float)n * (float)(tid - 3) * (1.0f / 512.0f); // in units of pi
        float s, c;
        sincospif(ang, &s, &c);
        ph[tid] = make_float2(c, s);
    }
    __syncthreads();
    for (int f = tid; f < LFFT; f += 256) {
        float gr = 0.f, gi = 0.f;
#pragma unroll
        for (int q = 0; q < 7; q++) {
            float2 b = g_B[q * LFFT + f];
            float2 p = ph[q];
            gr += p.x * b.x - p.y * b.y;
            gi += p.x * b.y + p.y * b.x;
        }
        g_G[n * LFFT + f] = make_float2(gr * (1.0f / (float)LFFT), gi * (1.0f / (float)LFFT));
    }
}

// ---------------- STFT: one frame per block, 512-pt DIF radix-2 FFT with shared twiddles ----------------
__global__ __launch_bounds__(256) void stft_kernel(const float* __restrict__ wav,
                                                   const float* __restrict__ win) {
    __shared__ float sRe[NFFT], sIm[NFFT];
    __shared__ float2 sTw[1024];
    int t   = blockIdx.x;   // 0..1024
    int b   = blockIdx.y;   // 0..3
    int tid = threadIdx.x;  // 256 threads

    for (int i = tid; i < 1024; i += 256) sTw[i] = g_tw[i];
    for (int i = tid; i < NFFT; i += 256) {
        int p = t * HOPSZ + i - 256;
        if (p < 0) p = -p;
        if (p >= LSAMP) p = 2 * LSAMP - 2 - p;
        sRe[i] = wav[b * LSAMP + p] * win[i];
        sIm[i] = 0.f;
    }

    int mult = 4;  // 1024 / 256
    for (int s = 256; s >= 1; s >>= 1, mult <<= 1) {
        __syncthreads();
        int j  = tid & (s - 1);
        int i0 = ((tid - j) << 1) + j;
        float2 w = sTw[j * mult];
        float ar = sRe[i0],     ai = sIm[i0];
        float br = sRe[i0 + s], bi = sIm[i0 + s];
        sRe[i0] = ar + br;  sIm[i0] = ai + bi;
        float dr = ar - br, di = ai - bi;
        sRe[i0 + s] = dr * w.x - di * w.y;
        sIm[i0 + s] = dr * w.y + di * w.x;
    }
    __syncthreads();

    // position i holds bin n = bitrev9(i)
    for (int i = tid; i < NFFT; i += 256) {
        int n = (int)(__brev((unsigned)i) >> 23);
        g_H[(b * NFFT + n) * TFRAMES + t] = make_float2(sRe[i], sIm[i]);
    }
}

// ---------------- conv via FFT: one (b,n) row per block ----------------
__global__ __launch_bounds__(512) void conv_kernel() {
    __shared__ float sRe[LFFT], sIm[LFFT];
    __shared__ float2 sTw[1024];
    __shared__ float warpsum[16];

    int row = blockIdx.x;        // b*512 + n
    int tid = threadIdx.x;       // 512 threads

    for (int i = tid; i < 1024; i += 512) sTw[i] = g_tw[i];
    const float2* __restrict__ Hrow = &g_H[row * TFRAMES];
    for (int i = tid; i < LFFT; i += 512) {
        if (i < TFRAMES) { float2 h = Hrow[i]; sRe[i] = h.x; sIm[i] = h.y; }
        else             { sRe[i] = 0.f;       sIm[i] = 0.f; }
    }

    fft2048_fwd(sRe, sIm, sTw, tid);
    __syncthreads();

    // pointwise multiply by G[n] (both in bit-reversed order)
    const float2* __restrict__ Gr = &g_G[(row & (NFFT - 1)) * LFFT];
#pragma unroll
    for (int r = 0; r < 4; r++) {
        int i = tid + r * 512;
        float2 g = Gr[i];
        float xr = sRe[i], xi = sIm[i];
        sRe[i] = xr * g.x - xi * g.y;
        sIm[i] = xr * g.y + xi * g.x;
    }

    fft2048_inv(sRe, sIm, sTw, tid);
    __syncthreads();

    // c[m] natural order; valid circular lags: m in [0,513] U [1537,2047]
    float lsum = 0.f;
#pragma unroll
    for (int r = 0; r < 4; r++) {
        int i = tid + r * 512;
        if (i <= 513 || i >= 1537) {
            float cr = sRe[i], ci = sIm[i];
            lsum += cr * cr + ci * ci;
        }
    }

#pragma unroll
    for (int off = 16; off > 0; off >>= 1)
        lsum += __shfl_down_sync(0xffffffff, lsum, off);
    if ((tid & 31) == 0) warpsum[tid >> 5] = lsum;
    __syncthreads();
    if (tid == 0) {
        float s = 0.f;
#pragma unroll
        for (int w = 0; w < 16; w++) s += warpsum[w];
        atomicAdd(&g_acc, (double)s);
    }
}

__global__ void finalize_kernel(float* out) {
    out[0] = (float)(g_acc / (double)(BATCH * TFRAMES));
}

extern "C" void kernel_launch(void* const* d_in, const int* in_sizes, int n_in,
                              void* d_out, int out_size) {
    const float* wav = (const float*)d_in[0];
    const float* win = (const float*)d_in[1];
    const float* ar  = (const float*)d_in[2];
    const float* ai  = (const float*)d_in[3];

    reset_kernel<<<1, 1>>>();
    twinit_kernel<<<4, 256>>>();
    alphafft_kernel<<<7, 512>>>(ar, ai);
    gcomb_kernel<<<NFFT, 256>>>();
    dim3 gs(TFRAMES, BATCH);
    stft_kernel<<<gs, 256>>>(wav, win);
    conv_kernel<<<NROWS, 512>>>();
    finalize_kernel<<<1, 1>>>((float*)d_out);
}

// round 3
// speedup vs baseline: 4.2741x; 2.1826x over previous
#include <cuda_runtime.h>

#define NFFT    512
#define HOPSZ   128
#define BATCH   4
#define LSAMP   131072
#define TFRAMES 1025
#define KW      1023
#define NROWS   (BATCH * NFFT)   // 2048
#define LFFT    2048

// smem swizzle: bijection on [0,2048), conflict-free for all stage patterns
#define SW(i) ((i) ^ (((((i) >> 5) & 7)) | ((((i) >> 5) & 3) << 3)))

// per-stage twiddle table offsets in g_stw: entry j of stage s = exp(-2pi i j/(4s))
#define T512 0
#define T128 512
#define T32  640
#define T8   672
#define TWN  680

// ------------- device scratch (static, no allocs) -------------
__device__ float2 g_H[BATCH * NFFT * TFRAMES];  // [b][n][t]
__device__ float2 g_B[7 * LFFT];                // FFT'd alpha rows (scrambled order)
__device__ float2 g_G[NFFT * LFFT];             // per-bin spectrum (scrambled order)
__device__ float2 g_tw[1024];                   // radix-2 table for stft
__device__ float2 g_stw[TWN];                   // per-stage radix-4 tables
__device__ double g_acc;

__global__ void reset_kernel() { g_acc = 0.0; }

__global__ void twinit_kernel() {
    int i = blockIdx.x * blockDim.x + threadIdx.x;
    if (i < 1024) {
        float s, c;
        sincospif(-(float)i * (1.0f / 1024.0f), &s, &c);
        g_tw[i] = make_float2(c, s);
    }
    if (i < TWN) {
        int j, M;
        if (i < T128)      { j = i;        M = 2048; }
        else if (i < T32)  { j = i - T128; M = 512;  }
        else if (i < T8)   { j = i - T32;  M = 128;  }
        else               { j = i - T8;   M = 32;   }
        float s, c;
        sincospif(-2.0f * (float)j / (float)M, &s, &c);
        g_stw[i] = make_float2(c, s);
    }
}

__device__ __forceinline__ float2 cmul(float2 a, float2 b) {
    return make_float2(a.x * b.x - a.y * b.y, a.x * b.y + a.y * b.x);
}
__device__ __forceinline__ float2 cadd(float2 a, float2 b) { return make_float2(a.x + b.x, a.y + b.y); }
__device__ __forceinline__ float2 csub(float2 a, float2 b) { return make_float2(a.x - b.x, a.y - b.y); }
__device__ __forceinline__ float2 cnegi(float2 a) { return make_float2(a.y, -a.x); }   // -i*a
__device__ __forceinline__ float2 cposi(float2 a) { return make_float2(-a.y, a.x); }   // +i*a

// forward DIF radix-4 smem stage (span s), 512 threads = 512 butterflies
template<int S, int TOFF>
__device__ __forceinline__ void r4_fwd(float2* sD, const float2* __restrict__ stw, int tid) {
    int j  = tid & (S - 1);
    int i0 = ((tid - j) << 2) + j;
    float2 w  = stw[TOFF + j];
    float2 w2 = cmul(w, w);
    float2 w3 = cmul(w2, w);
    float2 a = sD[SW(i0)], b = sD[SW(i0 + S)], c = sD[SW(i0 + 2 * S)], d = sD[SW(i0 + 3 * S)];
    float2 t0 = cadd(a, c), t1 = csub(a, c);
    float2 t2 = cadd(b, d), u3 = cnegi(csub(b, d));
    sD[SW(i0)]         = cadd(t0, t2);
    sD[SW(i0 + S)]     = cmul(cadd(t1, u3), w);
    sD[SW(i0 + 2 * S)] = cmul(csub(t0, t2), w2);
    sD[SW(i0 + 3 * S)] = cmul(csub(t1, u3), w3);
}

// inverse radix-4 smem stage (span s)
template<int S, int TOFF>
__device__ __forceinline__ void r4_inv(float2* sD, const float2* __restrict__ stw, int tid) {
    int j  = tid & (S - 1);
    int i0 = ((tid - j) << 2) + j;
    float2 w = stw[TOFF + j];
    w.y = -w.y;                       // conj
    float2 w2 = cmul(w, w);
    float2 w3 = cmul(w2, w);
    float2 a = sD[SW(i0)];
    float2 b = cmul(sD[SW(i0 + S)], w);
    float2 c = cmul(sD[SW(i0 + 2 * S)], w2);
    float2 d = cmul(sD[SW(i0 + 3 * S)], w3);
    float2 t0 = cadd(a, c), t1 = csub(a, c);
    float2 t2 = cadd(b, d), v3 = cposi(csub(b, d));
    sD[SW(i0)]         = cadd(t0, t2);
    sD[SW(i0 + S)]     = cadd(t1, v3);
    sD[SW(i0 + 2 * S)] = csub(t0, t2);
    sD[SW(i0 + 3 * S)] = csub(t1, v3);
}

// fwd 8-pt tail (radix-4 s=2 + radix-2 s=1) on registers z[0..7]; outputs X in-place
__device__ __forceinline__ void fwd8(float2* z) {
    const float r = 0.70710678118654752f;
    const float2 W1 = make_float2(r, -r);        // e^{-i pi/4}
    const float2 W3 = make_float2(-r, -r);       // e^{-i 3pi/4}
    // radix-4 s=2, j=0 on (0,2,4,6)
    float2 t0 = cadd(z[0], z[4]), t1 = csub(z[0], z[4]);
    float2 t2 = cadd(z[2], z[6]), u3 = cnegi(csub(z[2], z[6]));
    float2 p0 = cadd(t0, t2), p2 = cadd(t1, u3), p4 = csub(t0, t2), p6 = csub(t1, u3);
    // j=1 on (1,3,5,7): y1*=W1, y2*=-i, y3*=W3
    t0 = cadd(z[1], z[5]); t1 = csub(z[1], z[5]);
    t2 = cadd(z[3], z[7]); u3 = cnegi(csub(z[3], z[7]));
    float2 p1 = cadd(t0, t2);
    float2 p3 = cmul(cadd(t1, u3), W1);
    float2 p5 = cnegi(csub(t0, t2));
    float2 p7 = cmul(csub(t1, u3), W3);
    // radix-2 s=1 pairs
    z[0] = cadd(p0, p1); z[1] = csub(p0, p1);
    z[2] = cadd(p2, p3); z[3] = csub(p2, p3);
    z[4] = cadd(p4, p5); z[5] = csub(p4, p5);
    z[6] = cadd(p6, p7); z[7] = csub(p6, p7);
}

// inverse 8-pt head (inv radix-2 s=1 + inv radix-4 s=2) on registers
__device__ __forceinline__ void inv8(float2* z) {
    const float r = 0.70710678118654752f;
    const float2 W1c = make_float2(r, r);        // conj(e^{-i pi/4})
    const float2 W3c = make_float2(-r, r);       // conj(e^{-i 3pi/4})
    float2 q0 = cadd(z[0], z[1]), q1 = csub(z[0], z[1]);
    float2 q2 = cadd(z[2], z[3]), q3 = csub(z[2], z[3]);
    float2 q4 = cadd(z[4], z[5]), q5 = csub(z[4], z[5]);
    float2 q6 = cadd(z[6], z[7]), q7 = csub(z[6], z[7]);
    // inv radix-4 s=2, j=0 on (q0,q2,q4,q6)
    float2 t0 = cadd(q0, q4), t1 = csub(q0, q4);
    float2 t2 = cadd(q2, q6), v3 = cposi(csub(q2, q6));
    z[0] = cadd(t0, t2); z[2] = cadd(t1, v3); z[4] = csub(t0, t2); z[6] = csub(t1, v3);
    // j=1 on (q1,q3,q5,q7) with conj twiddles
    float2 b = cmul(q3, W1c);
    float2 c = cposi(q5);
    float2 d = cmul(q7, W3c);
    t0 = cadd(q1, c); t1 = csub(q1, c);
    t2 = cadd(b, d);  v3 = cposi(csub(b, d));
    z[1] = cadd(t0, t2); z[3] = cadd(t1, v3); z[5] = csub(t0, t2); z[7] = csub(t1, v3);
}

// ---------------- FFT of the 7 conjugated alpha rows ----------------
__global__ __launch_bounds__(512) void alphafft_kernel(const float* __restrict__ ar,
                                                       const float* __restrict__ ai) {
    __shared__ float2 sD[LFFT];
    const float2* __restrict__ stw = g_stw;
    int q = blockIdx.x, tid = threadIdx.x;

    // reg stage s=512 from global conj(alpha), zero-padded
    float2 a = make_float2(ar[q * KW + tid], -ai[q * KW + tid]);          // tid < 1023 always
    float2 b = make_float2(0.f, 0.f);
    if (tid + 512 < KW) b = make_float2(ar[q * KW + tid + 512], -ai[q * KW + tid + 512]);
    float2 w  = stw[T512 + tid];
    float2 w2 = cmul(w, w);
    float2 w3 = cmul(w2, w);
    float2 t0 = a;            // a + c, c=0
    float2 t1 = a;
    float2 t2 = b;            // b + d, d=0
    float2 u3 = cnegi(b);
    sD[SW(tid)]        = cadd(t0, t2);
    sD[SW(tid + 512)]  = cmul(cadd(t1, u3), w);
    sD[SW(tid + 1024)] = cmul(csub(t0, t2), w2);
    sD[SW(tid + 1536)] = cmul(csub(t1, u3), w3);
    __syncthreads();
    r4_fwd<128, T128>(sD, stw, tid); __syncthreads();
    r4_fwd<32,  T32 >(sD, stw, tid); __syncthreads();
    r4_fwd<8,   T8  >(sD, stw, tid); __syncthreads();

    if (tid < 256) {
        float2 z[8];
#pragma unroll
        for (int c = 0; c < 8; c++) z[c] = sD[SW(8 * tid + c)];
        fwd8(z);
        float2* __restrict__ out = &g_B[q * LFFT + 8 * tid];
#pragma unroll
        for (int c = 0; c < 8; c++) {
            float2 v = z[c];
            out[c] = make_float2(v.x, -v.y);     // conj
        }
    }
}

// ---------------- G[n,f] = (1/L) sum_q e^{+2pi i n(q-3)/512} B[q,f] ----------------
__global__ __launch_bounds__(128) void gcomb_kernel() {
    int f  = blockIdx.x * 128 + threadIdx.x;
    int n0 = blockIdx.y * 64;
    float2 Bq[7], p[7], st[7];
#pragma unroll
    for (int q = 0; q < 7; q++) {
        Bq[q] = g_B[q * LFFT + f];
        float qq = (float)(q - 3);
        float s, c;
        sincospif((float)n0 * qq * (1.0f / 256.0f), &s, &c);
        p[q] = make_float2(c, s);
        sincospif(qq * (1.0f / 256.0f), &s, &c);
        st[q] = make_float2(c, s);
    }
    float2* __restrict__ out = &g_G[n0 * LFFT + f];
    for (int n = 0; n < 64; n++) {
        float gr = 0.f, gi = 0.f;
#pragma unroll
        for (int q = 0; q < 7; q++) {
            gr += p[q].x * Bq[q].x - p[q].y * Bq[q].y;
            gi += p[q].x * Bq[q].y + p[q].y * Bq[q].x;
        }
        out[(size_t)n * LFFT] = make_float2(gr * (1.0f / (float)LFFT), gi * (1.0f / (float)LFFT));
#pragma unroll
        for (int q = 0; q < 7; q++) p[q] = cmul(p[q], st[q]);
    }
}

// ---------------- STFT: one frame per block, 512-pt radix-2 (unchanged) ----------------
__global__ __launch_bounds__(256) void stft_kernel(const float* __restrict__ wav,
                                                   const float* __restrict__ win) {
    __shared__ float sRe[NFFT], sIm[NFFT];
    __shared__ float2 sTw[1024];
    int t = blockIdx.x, b = blockIdx.y, tid = threadIdx.x;

    for (int i = tid; i < 1024; i += 256) sTw[i] = g_tw[i];
    for (int i = tid; i < NFFT; i += 256) {
        int p = t * HOPSZ + i - 256;
        if (p < 0) p = -p;
        if (p >= LSAMP) p = 2 * LSAMP - 2 - p;
        sRe[i] = wav[b * LSAMP + p] * win[i];
        sIm[i] = 0.f;
    }
    int mult = 4;
    for (int s = 256; s >= 1; s >>= 1, mult <<= 1) {
        __syncthreads();
        int j  = tid & (s - 1);
        int i0 = ((tid - j) << 1) + j;
        float2 w = sTw[j * mult];
        float ar = sRe[i0],     ai = sIm[i0];
        float br = sRe[i0 + s], bi = sIm[i0 + s];
        sRe[i0] = ar + br;  sIm[i0] = ai + bi;
        float dr = ar - br, di = ai - bi;
        sRe[i0 + s] = dr * w.x - di * w.y;
        sIm[i0 + s] = dr * w.y + di * w.x;
    }
    __syncthreads();
    for (int i = tid; i < NFFT; i += 256) {
        int n = (int)(__brev((unsigned)i) >> 23);
        g_H[(b * NFFT + n) * TFRAMES + t] = make_float2(sRe[i], sIm[i]);
    }
}

// ---------------- conv via radix-4 FFT: one (b,n) row per block ----------------
__global__ __launch_bounds__(512) void conv_kernel() {
    __shared__ float2 sD[LFFT];
    __shared__ float warpsum[16];
    const float2* __restrict__ stw = g_stw;

    int row = blockIdx.x;
    int tid = threadIdx.x;

    // ---- fwd reg stage s=512, fused with global load ----
    const float2* __restrict__ Hrow = &g_H[row * TFRAMES];
    float2 a = Hrow[tid];
    float2 b = Hrow[tid + 512];
    float2 c = (tid == 0) ? Hrow[1024] : make_float2(0.f, 0.f);
    {
        float2 w  = stw[T512 + tid];
        float2 w2 = cmul(w, w);
        float2 w3 = cmul(w2, w);
        float2 t0 = cadd(a, c), t1 = csub(a, c);
        float2 t2 = b,          u3 = cnegi(b);      // d = 0
        sD[SW(tid)]        = cadd(t0, t2);
        sD[SW(tid + 512)]  = cmul(cadd(t1, u3), w);
        sD[SW(tid + 1024)] = cmul(csub(t0, t2), w2);
        sD[SW(tid + 1536)] = cmul(csub(t1, u3), w3);
    }
    __syncthreads();
    r4_fwd<128, T128>(sD, stw, tid); __syncthreads();
    r4_fwd<32,  T32 >(sD, stw, tid); __syncthreads();
    r4_fwd<8,   T8  >(sD, stw, tid); __syncthreads();

    // ---- mega-fused: fwd 8-pt tail + pointwise * G + inv 8-pt head ----
    if (tid < 256) {
        float2 z[8];
#pragma unroll
        for (int cc = 0; cc < 8; cc++) z[cc] = sD[SW(8 * tid + cc)];
        fwd8(z);
        const float4* __restrict__ Gr =
            (const float4*)&g_G[(row & (NFFT - 1)) * LFFT + 8 * tid];
#pragma unroll
        for (int cc = 0; cc < 4; cc++) {
            float4 g = Gr[cc];
            float2 x0 = z[2 * cc], x1 = z[2 * cc + 1];
            z[2 * cc]     = make_float2(x0.x * g.x - x0.y * g.y, x0.x * g.y + x0.y * g.x);
            z[2 * cc + 1] = make_float2(x1.x * g.z - x1.y * g.w, x1.x * g.w + x1.y * g.z);
        }
        inv8(z);
#pragma unroll
        for (int cc = 0; cc < 8; cc++) sD[SW(8 * tid + cc)] = z[cc];
    }
    __syncthreads();
    r4_inv<8,   T8  >(sD, stw, tid); __syncthreads();
    r4_inv<32,  T32 >(sD, stw, tid); __syncthreads();
    r4_inv<128, T128>(sD, stw, tid); __syncthreads();

    // ---- inv reg stage s=512 + |c|^2 accumulation with lag validity ----
    float lsum;
    {
        float2 w = stw[T512 + tid];
        w.y = -w.y;
        float2 w2 = cmul(w, w);
        float2 w3 = cmul(w2, w);
        float2 ya = sD[SW(tid)];
        float2 yb = cmul(sD[SW(tid + 512)], w);
        float2 yc = cmul(sD[SW(tid + 1024)], w2);
        float2 yd = cmul(sD[SW(tid + 1536)], w3);
        float2 t0 = cadd(ya, yc), t1 = csub(ya, yc);
        float2 t2 = cadd(yb, yd), v3 = cposi(csub(yb, yd));
        float2 x0 = cadd(t0, t2);                  // lag tid       : always valid
        float2 x1 = cadd(t1, v3);                  // lag tid+512   : valid iff tid<2
        float2 x3 = csub(t1, v3);                  // lag tid+1536  : valid iff tid>=1
        lsum = x0.x * x0.x + x0.y * x0.y;
        if (tid < 2)  lsum += x1.x * x1.x + x1.y * x1.y;
        if (tid >= 1) lsum += x3.x * x3.x + x3.y * x3.y;
    }

#pragma unroll
    for (int off = 16; off > 0; off >>= 1)
        lsum += __shfl_down_sync(0xffffffff, lsum, off);
    if ((tid & 31) == 0) warpsum[tid >> 5] = lsum;
    __syncthreads();
    if (tid == 0) {
        float s = 0.f;
#pragma unroll
        for (int w = 0; w < 16; w++) s += warpsum[w];
        atomicAdd(&g_acc, (double)s);
    }
}

__global__ void finalize_kernel(float* out) {
    out[0] = (float)(g_acc / (double)(BATCH * TFRAMES));
}

extern "C" void kernel_launch(void* const* d_in, const int* in_sizes, int n_in,
                              void* d_out, int out_size) {
    const float* wav = (const float*)d_in[0];
    const float* win = (const float*)d_in[1];
    const float* ar  = (const float*)d_in[2];
    const float* ai  = (const float*)d_in[3];

    reset_kernel<<<1, 1>>>();
    twinit_kernel<<<4, 256>>>();
    alphafft_kernel<<<7, 512>>>(ar, ai);
    dim3 gG(LFFT / 128, NFFT / 64);
    gcomb_kernel<<<gG, 128>>>();
    dim3 gs(TFRAMES, BATCH);
    stft_kernel<<<gs, 256>>>(wav, win);
    conv_kernel<<<NROWS, 512>>>();
    finalize_kernel<<<1, 1>>>((float*)d_out);
}

// round 4
// speedup vs baseline: 5.5226x; 1.2921x over previous
#include <cuda_runtime.h>

#define NFFT    512
#define HOPSZ   128
#define BATCH   4
#define LSAMP   131072
#define TFRAMES 1025
#define KW      1023
#define NROWS   (BATCH * NFFT)   // 2048
#define LFFT    2048

// smem swizzle: bijection on [0,2048), conflict-free for all stage patterns
#define SW(i) ((i) ^ (((((i) >> 5) & 7)) | ((((i) >> 5) & 3) << 3)))

// per-stage twiddle table offsets in g_stw: entry j of stage s = exp(-2pi i j/(4s))
#define T512 0
#define T128 512
#define T32  640
#define T8   672
#define TWN  680

// ------------- device scratch (static, no allocs) -------------
__device__ float2 g_H[BATCH * NFFT * TFRAMES];  // [b][n][t]
__device__ float2 g_B[7 * LFFT];                // FFT'd alpha rows (scrambled order)
__device__ float2 g_G[NFFT * LFFT];             // per-bin spectrum (scrambled order)
__device__ float2 g_tw[1024];                   // radix-2 table for stft
__device__ float2 g_stw[TWN];                   // per-stage radix-4 tables
__device__ double g_acc;

__global__ void twinit_kernel() {
    int i = blockIdx.x * blockDim.x + threadIdx.x;
    if (i == 0) g_acc = 0.0;
    if (i < 1024) {
        float s, c;
        sincospif(-(float)i * (1.0f / 1024.0f), &s, &c);
        g_tw[i] = make_float2(c, s);
    }
    if (i < TWN) {
        int j, M;
        if (i < T128)      { j = i;        M = 2048; }
        else if (i < T32)  { j = i - T128; M = 512;  }
        else if (i < T8)   { j = i - T32;  M = 128;  }
        else               { j = i - T8;   M = 32;   }
        float s, c;
        sincospif(-2.0f * (float)j / (float)M, &s, &c);
        g_stw[i] = make_float2(c, s);
    }
}

__device__ __forceinline__ float2 cmul(float2 a, float2 b) {
    return make_float2(a.x * b.x - a.y * b.y, a.x * b.y + a.y * b.x);
}
__device__ __forceinline__ float2 cadd(float2 a, float2 b) { return make_float2(a.x + b.x, a.y + b.y); }
__device__ __forceinline__ float2 csub(float2 a, float2 b) { return make_float2(a.x - b.x, a.y - b.y); }
__device__ __forceinline__ float2 cnegi(float2 a) { return make_float2(a.y, -a.x); }   // -i*a
__device__ __forceinline__ float2 cposi(float2 a) { return make_float2(-a.y, a.x); }   // +i*a

// forward DIF radix-4 smem stage (span s), 512 threads = 512 butterflies
template<int S, int TOFF>
__device__ __forceinline__ void r4_fwd(float2* sD, const float2* __restrict__ stw, int tid) {
    int j  = tid & (S - 1);
    int i0 = ((tid - j) << 2) + j;
    float2 w  = stw[TOFF + j];
    float2 w2 = cmul(w, w);
    float2 w3 = cmul(w2, w);
    float2 a = sD[SW(i0)], b = sD[SW(i0 + S)], c = sD[SW(i0 + 2 * S)], d = sD[SW(i0 + 3 * S)];
    float2 t0 = cadd(a, c), t1 = csub(a, c);
    float2 t2 = cadd(b, d), u3 = cnegi(csub(b, d));
    sD[SW(i0)]         = cadd(t0, t2);
    sD[SW(i0 + S)]     = cmul(cadd(t1, u3), w);
    sD[SW(i0 + 2 * S)] = cmul(csub(t0, t2), w2);
    sD[SW(i0 + 3 * S)] = cmul(csub(t1, u3), w3);
}

// inverse radix-4 smem stage (span s)
template<int S, int TOFF>
__device__ __forceinline__ void r4_inv(float2* sD, const float2* __restrict__ stw, int tid) {
    int j  = tid & (S - 1);
    int i0 = ((tid - j) << 2) + j;
    float2 w = stw[TOFF + j];
    w.y = -w.y;                       // conj
    float2 w2 = cmul(w, w);
    float2 w3 = cmul(w2, w);
    float2 a = sD[SW(i0)];
    float2 b = cmul(sD[SW(i0 + S)], w);
    float2 c = cmul(sD[SW(i0 + 2 * S)], w2);
    float2 d = cmul(sD[SW(i0 + 3 * S)], w3);
    float2 t0 = cadd(a, c), t1 = csub(a, c);
    float2 t2 = cadd(b, d), v3 = cposi(csub(b, d));
    sD[SW(i0)]         = cadd(t0, t2);
    sD[SW(i0 + S)]     = cadd(t1, v3);
    sD[SW(i0 + 2 * S)] = csub(t0, t2);
    sD[SW(i0 + 3 * S)] = csub(t1, v3);
}

// fwd 8-pt tail on registers z[0..7]
__device__ __forceinline__ void fwd8(float2* z) {
    const float r = 0.70710678118654752f;
    const float2 W1 = make_float2(r, -r);
    const float2 W3 = make_float2(-r, -r);
    float2 t0 = cadd(z[0], z[4]), t1 = csub(z[0], z[4]);
    float2 t2 = cadd(z[2], z[6]), u3 = cnegi(csub(z[2], z[6]));
    float2 p0 = cadd(t0, t2), p2 = cadd(t1, u3), p4 = csub(t0, t2), p6 = csub(t1, u3);
    t0 = cadd(z[1], z[5]); t1 = csub(z[1], z[5]);
    t2 = cadd(z[3], z[7]); u3 = cnegi(csub(z[3], z[7]));
    float2 p1 = cadd(t0, t2);
    float2 p3 = cmul(cadd(t1, u3), W1);
    float2 p5 = cnegi(csub(t0, t2));
    float2 p7 = cmul(csub(t1, u3), W3);
    z[0] = cadd(p0, p1); z[1] = csub(p0, p1);
    z[2] = cadd(p2, p3); z[3] = csub(p2, p3);
    z[4] = cadd(p4, p5); z[5] = csub(p4, p5);
    z[6] = cadd(p6, p7); z[7] = csub(p6, p7);
}

// inverse 8-pt head on registers
__device__ __forceinline__ void inv8(float2* z) {
    const float r = 0.70710678118654752f;
    const float2 W1c = make_float2(r, r);
    const float2 W3c = make_float2(-r, r);
    float2 q0 = cadd(z[0], z[1]), q1 = csub(z[0], z[1]);
    float2 q2 = cadd(z[2], z[3]), q3 = csub(z[2], z[3]);
    float2 q4 = cadd(z[4], z[5]), q5 = csub(z[4], z[5]);
    float2 q6 = cadd(z[6], z[7]), q7 = csub(z[6], z[7]);
    float2 t0 = cadd(q0, q4), t1 = csub(q0, q4);
    float2 t2 = cadd(q2, q6), v3 = cposi(csub(q2, q6));
    z[0] = cadd(t0, t2); z[2] = cadd(t1, v3); z[4] = csub(t0, t2); z[6] = csub(t1, v3);
    float2 b = cmul(q3, W1c);
    float2 c = cposi(q5);
    float2 d = cmul(q7, W3c);
    t0 = cadd(q1, c); t1 = csub(q1, c);
    t2 = cadd(b, d);  v3 = cposi(csub(b, d));
    z[1] = cadd(t0, t2); z[3] = cadd(t1, v3); z[5] = csub(t0, t2); z[7] = csub(t1, v3);
}

// ---------------- FFT of the 7 conjugated alpha rows ----------------
__global__ __launch_bounds__(512) void alphafft_kernel(const float* __restrict__ ar,
                                                       const float* __restrict__ ai) {
    __shared__ float2 sD[LFFT];
    const float2* __restrict__ stw = g_stw;
    int q = blockIdx.x, tid = threadIdx.x;

    float2 a = make_float2(ar[q * KW + tid], -ai[q * KW + tid]);
    float2 b = make_float2(0.f, 0.f);
    if (tid + 512 < KW) b = make_float2(ar[q * KW + tid + 512], -ai[q * KW + tid + 512]);
    float2 w  = stw[T512 + tid];
    float2 w2 = cmul(w, w);
    float2 w3 = cmul(w2, w);
    float2 t2 = b;
    float2 u3 = cnegi(b);
    sD[SW(tid)]        = cadd(a, t2);
    sD[SW(tid + 512)]  = cmul(cadd(a, u3), w);
    sD[SW(tid + 1024)] = cmul(csub(a, t2), w2);
    sD[SW(tid + 1536)] = cmul(csub(a, u3), w3);
    __syncthreads();
    r4_fwd<128, T128>(sD, stw, tid); __syncthreads();
    r4_fwd<32,  T32 >(sD, stw, tid); __syncthreads();
    r4_fwd<8,   T8  >(sD, stw, tid); __syncthreads();

    if (tid < 256) {
        float2 z[8];
#pragma unroll
        for (int c = 0; c < 8; c++) z[c] = sD[SW(8 * tid + c)];
        fwd8(z);
        float2* __restrict__ out = &g_B[q * LFFT + 8 * tid];
#pragma unroll
        for (int c = 0; c < 8; c++) {
            float2 v = z[c];
            out[c] = make_float2(v.x, -v.y);     // conj
        }
    }
}

// ---------------- G[n,f] = (1/L) sum_q e^{+2pi i n(q-3)/512} B[q,f] ----------------
#define GN_PER 8
__global__ __launch_bounds__(128) void gcomb_kernel() {
    int f  = blockIdx.x * 128 + threadIdx.x;
    int n0 = blockIdx.y * GN_PER;
    float2 Bq[7], p[7], st[7];
#pragma unroll
    for (int q = 0; q < 7; q++) {
        Bq[q] = g_B[q * LFFT + f];
        float qq = (float)(q - 3);
        float s, c;
        sincospif((float)n0 * qq * (1.0f / 256.0f), &s, &c);
        p[q] = make_float2(c, s);
        sincospif(qq * (1.0f / 256.0f), &s, &c);
        st[q] = make_float2(c, s);
    }
    float2* __restrict__ out = &g_G[n0 * LFFT + f];
#pragma unroll
    for (int n = 0; n < GN_PER; n++) {
        float gr = 0.f, gi = 0.f;
#pragma unroll
        for (int q = 0; q < 7; q++) {
            gr += p[q].x * Bq[q].x - p[q].y * Bq[q].y;
            gi += p[q].x * Bq[q].y + p[q].y * Bq[q].x;
        }
        out[(size_t)n * LFFT] = make_float2(gr * (1.0f / (float)LFFT), gi * (1.0f / (float)LFFT));
#pragma unroll
        for (int q = 0; q < 7; q++) p[q] = cmul(p[q], st[q]);
    }
}

// ---------------- STFT: TWO real frames per complex 512-pt FFT ----------------
__global__ __launch_bounds__(256) void stft_kernel(const float* __restrict__ wav,
                                                   const float* __restrict__ win) {
    __shared__ float sRe[NFFT], sIm[NFFT];
    __shared__ float2 sTw[1024];
    int pr  = blockIdx.x;          // frame pair: frames (2pr, 2pr+1)
    int b   = blockIdx.y;
    int tid = threadIdx.x;
    int t0  = 2 * pr;
    bool has2 = (t0 + 1 < TFRAMES);

    for (int i = tid; i < 1024; i += 256) sTw[i] = g_tw[i];
    for (int i = tid; i < NFFT; i += 256) {
        int p0 = t0 * HOPSZ + i - 256;
        if (p0 < 0) p0 = -p0;
        if (p0 >= LSAMP) p0 = 2 * LSAMP - 2 - p0;
        float wv = win[i];
        sRe[i] = wav[b * LSAMP + p0] * wv;
        float v1 = 0.f;
        if (has2) {
            int p1 = (t0 + 1) * HOPSZ + i - 256;
            if (p1 < 0) p1 = -p1;
            if (p1 >= LSAMP) p1 = 2 * LSAMP - 2 - p1;
            v1 = wav[b * LSAMP + p1] * wv;
        }
        sIm[i] = v1;
    }
    int mult = 4;
    for (int s = 256; s >= 1; s >>= 1, mult <<= 1) {
        __syncthreads();
        int j  = tid & (s - 1);
        int i0 = ((tid - j) << 1) + j;
        float2 w = sTw[j * mult];
        float ar = sRe[i0],     ai = sIm[i0];
        float br = sRe[i0 + s], bi = sIm[i0 + s];
        sRe[i0] = ar + br;  sIm[i0] = ai + bi;
        float dr = ar - br, di = ai - bi;
        sRe[i0 + s] = dr * w.x - di * w.y;
        sIm[i0 + s] = dr * w.y + di * w.x;
    }
    __syncthreads();

    // unpack two real-frame spectra from the packed complex FFT
    for (int i = tid; i < NFFT; i += 256) {
        int n = (int)(__brev((unsigned)i) >> 23);
        int m = (NFFT - n) & (NFFT - 1);
        int j = (int)(__brev((unsigned)m) >> 23);
        float Znr = sRe[i], Zni = sIm[i];
        float Zmr = sRe[j], Zmi = sIm[j];
        float2 H0 = make_float2(0.5f * (Znr + Zmr), 0.5f * (Zni - Zmi));
        size_t base = (size_t)(b * NFFT + n) * TFRAMES + t0;
        g_H[base] = H0;
        if (has2) {
            float dr = Znr - Zmr, di = Zni + Zmi;
            g_H[base + 1] = make_float2(0.5f * di, -0.5f * dr);
        }
    }
}

// ---------------- conv via radix-4 FFT: one (b,n) row per block ----------------
__global__ __launch_bounds__(512, 2) void conv_kernel() {
    __shared__ float2 sD[LFFT];
    __shared__ float warpsum[16];
    const float2* __restrict__ stw = g_stw;

    int row = blockIdx.x;
    int tid = threadIdx.x;

    const float2* __restrict__ Hrow = &g_H[row * TFRAMES];
    float2 a = Hrow[tid];
    float2 b = Hrow[tid + 512];
    float2 c = (tid == 0) ? Hrow[1024] : make_float2(0.f, 0.f);
    {
        float2 w  = stw[T512 + tid];
        float2 w2 = cmul(w, w);
        float2 w3 = cmul(w2, w);
        float2 t0 = cadd(a, c), t1 = csub(a, c);
        float2 t2 = b,          u3 = cnegi(b);
        sD[SW(tid)]        = cadd(t0, t2);
        sD[SW(tid + 512)]  = cmul(cadd(t1, u3), w);
        sD[SW(tid + 1024)] = cmul(csub(t0, t2), w2);
        sD[SW(tid + 1536)] = cmul(csub(t1, u3), w3);
    }
    __syncthreads();
    r4_fwd<128, T128>(sD, stw, tid); __syncthreads();
    r4_fwd<32,  T32 >(sD, stw, tid); __syncthreads();
    r4_fwd<8,   T8  >(sD, stw, tid); __syncthreads();

    if (tid < 256) {
        float2 z[8];
#pragma unroll
        for (int cc = 0; cc < 8; cc++) z[cc] = sD[SW(8 * tid + cc)];
        fwd8(z);
        const float4* __restrict__ Gr =
            (const float4*)&g_G[(row & (NFFT - 1)) * LFFT + 8 * tid];
#pragma unroll
        for (int cc = 0; cc < 4; cc++) {
            float4 g = Gr[cc];
            float2 x0 = z[2 * cc], x1 = z[2 * cc + 1];
            z[2 * cc]     = make_float2(x0.x * g.x - x0.y * g.y, x0.x * g.y + x0.y * g.x);
            z[2 * cc + 1] = make_float2(x1.x * g.z - x1.y * g.w, x1.x * g.w + x1.y * g.z);
        }
        inv8(z);
#pragma unroll
        for (int cc = 0; cc < 8; cc++) sD[SW(8 * tid + cc)] = z[cc];
    }
    __syncthreads();
    r4_inv<8,   T8  >(sD, stw, tid); __syncthreads();
    r4_inv<32,  T32 >(sD, stw, tid); __syncthreads();
    r4_inv<128, T128>(sD, stw, tid); __syncthreads();

    float lsum;
    {
        float2 w = stw[T512 + tid];
        w.y = -w.y;
        float2 w2 = cmul(w, w);
        float2 w3 = cmul(w2, w);
        float2 ya = sD[SW(tid)];
        float2 yb = cmul(sD[SW(tid + 512)], w);
        float2 yc = cmul(sD[SW(tid + 1024)], w2);
        float2 yd = cmul(sD[SW(tid + 1536)], w3);
        float2 t0 = cadd(ya, yc), t1 = csub(ya, yc);
        float2 t2 = cadd(yb, yd), v3 = cposi(csub(yb, yd));
        float2 x0 = cadd(t0, t2);
        float2 x1 = cadd(t1, v3);
        float2 x3 = csub(t1, v3);
        lsum = x0.x * x0.x + x0.y * x0.y;
        if (tid < 2)  lsum += x1.x * x1.x + x1.y * x1.y;
        if (tid >= 1) lsum += x3.x * x3.x + x3.y * x3.y;
    }

#pragma unroll
    for (int off = 16; off > 0; off >>= 1)
        lsum += __shfl_down_sync(0xffffffff, lsum, off);
    if ((tid & 31) == 0) warpsum[tid >> 5] = lsum;
    __syncthreads();
    if (tid == 0) {
        float s = 0.f;
#pragma unroll
        for (int w = 0; w < 16; w++) s += warpsum[w];
        atomicAdd(&g_acc, (double)s);
    }
}

__global__ void finalize_kernel(float* out) {
    out[0] = (float)(g_acc / (double)(BATCH * TFRAMES));
}

extern "C" void kernel_launch(void* const* d_in, const int* in_sizes, int n_in,
                              void* d_out, int out_size) {
    const float* wav = (const float*)d_in[0];
    const float* win = (const float*)d_in[1];
    const float* ar  = (const float*)d_in[2];
    const float* ai  = (const float*)d_in[3];

    twinit_kernel<<<4, 256>>>();
    alphafft_kernel<<<7, 512>>>(ar, ai);
    dim3 gG(LFFT / 128, NFFT / GN_PER);
    gcomb_kernel<<<gG, 128>>>();
    dim3 gs((TFRAMES + 1) / 2, BATCH);
    stft_kernel<<<gs, 256>>>(wav, win);
    conv_kernel<<<NROWS, 512>>>();
    finalize_kernel<<<1, 1>>>((float*)d_out);
}

// round 5
// speedup vs baseline: 5.6888x; 1.0301x over previous
#include <cuda_runtime.h>

#define NFFT    512
#define HOPSZ   128
#define BATCH   4
#define LSAMP   131072
#define TFRAMES 1025
#define KW      1023
#define NROWS   (BATCH * NFFT)   // 2048
#define LFFT    2048
#define TCH     16               // t per chunk in tiled H layout
#define NCHUNK  65               // 65*16 = 1040 >= 1025

// smem swizzle: bijection on [0,2048), conflict-free for all stage patterns
#define SW(i) ((i) ^ (((((i) >> 5) & 7)) | ((((i) >> 5) & 3) << 3)))

// per-stage twiddle table offsets in g_stw: entry j of stage s = exp(-2pi i j/(4s))
#define T512 0
#define T128 512
#define T32  640
#define T8   672
#define TWN  680

// ------------- device scratch (static, no allocs) -------------
__device__ float2 g_Ht[NCHUNK * NROWS * TCH];   // tiled: [chunk][row][16]
__device__ float2 g_B[7 * LFFT];                // FFT'd alpha rows (scrambled order)
__device__ float2 g_G[NFFT * LFFT];             // per-bin spectrum (scrambled order)
__device__ float2 g_tw512[256];                 // exp(-i pi x/256) for 512-pt FFT
__device__ float2 g_stw[TWN];                   // per-stage radix-4 tables (2048-pt)
__device__ double g_acc;

__global__ void twinit_kernel() {
    int i = blockIdx.x * blockDim.x + threadIdx.x;
    if (i == 0) g_acc = 0.0;
    if (i < 256) {
        float s, c;
        sincospif(-(float)i * (1.0f / 256.0f), &s, &c);
        g_tw512[i] = make_float2(c, s);
    }
    if (i < TWN) {
        int j, M;
        if (i < T128)      { j = i;        M = 2048; }
        else if (i < T32)  { j = i - T128; M = 512;  }
        else if (i < T8)   { j = i - T32;  M = 128;  }
        else               { j = i - T8;   M = 32;   }
        float s, c;
        sincospif(-2.0f * (float)j / (float)M, &s, &c);
        g_stw[i] = make_float2(c, s);
    }
}

__device__ __forceinline__ float2 cmul(float2 a, float2 b) {
    return make_float2(a.x * b.x - a.y * b.y, a.x * b.y + a.y * b.x);
}
__device__ __forceinline__ float2 cadd(float2 a, float2 b) { return make_float2(a.x + b.x, a.y + b.y); }
__device__ __forceinline__ float2 csub(float2 a, float2 b) { return make_float2(a.x - b.x, a.y - b.y); }
__device__ __forceinline__ float2 cnegi(float2 a) { return make_float2(a.y, -a.x); }   // -i*a
__device__ __forceinline__ float2 cposi(float2 a) { return make_float2(-a.y, a.x); }   // +i*a

// forward DIF radix-4 smem stage (span s), 512 threads = 512 butterflies
template<int S, int TOFF>
__device__ __forceinline__ void r4_fwd(float2* sD, const float2* __restrict__ stw, int tid) {
    int j  = tid & (S - 1);
    int i0 = ((tid - j) << 2) + j;
    float2 w  = stw[TOFF + j];
    float2 w2 = cmul(w, w);
    float2 w3 = cmul(w2, w);
    float2 a = sD[SW(i0)], b = sD[SW(i0 + S)], c = sD[SW(i0 + 2 * S)], d = sD[SW(i0 + 3 * S)];
    float2 t0 = cadd(a, c), t1 = csub(a, c);
    float2 t2 = cadd(b, d), u3 = cnegi(csub(b, d));
    sD[SW(i0)]         = cadd(t0, t2);
    sD[SW(i0 + S)]     = cmul(cadd(t1, u3), w);
    sD[SW(i0 + 2 * S)] = cmul(csub(t0, t2), w2);
    sD[SW(i0 + 3 * S)] = cmul(csub(t1, u3), w3);
}

// inverse radix-4 smem stage (span s)
template<int S, int TOFF>
__device__ __forceinline__ void r4_inv(float2* sD, const float2* __restrict__ stw, int tid) {
    int j  = tid & (S - 1);
    int i0 = ((tid - j) << 2) + j;
    float2 w = stw[TOFF + j];
    w.y = -w.y;                       // conj
    float2 w2 = cmul(w, w);
    float2 w3 = cmul(w2, w);
    float2 a = sD[SW(i0)];
    float2 b = cmul(sD[SW(i0 + S)], w);
    float2 c = cmul(sD[SW(i0 + 2 * S)], w2);
    float2 d = cmul(sD[SW(i0 + 3 * S)], w3);
    float2 t0 = cadd(a, c), t1 = csub(a, c);
    float2 t2 = cadd(b, d), v3 = cposi(csub(b, d));
    sD[SW(i0)]         = cadd(t0, t2);
    sD[SW(i0 + S)]     = cadd(t1, v3);
    sD[SW(i0 + 2 * S)] = csub(t0, t2);
    sD[SW(i0 + 3 * S)] = csub(t1, v3);
}

// fwd 8-pt tail on registers z[0..7]
__device__ __forceinline__ void fwd8(float2* z) {
    const float r = 0.70710678118654752f;
    const float2 W1 = make_float2(r, -r);
    const float2 W3 = make_float2(-r, -r);
    float2 t0 = cadd(z[0], z[4]), t1 = csub(z[0], z[4]);
    float2 t2 = cadd(z[2], z[6]), u3 = cnegi(csub(z[2], z[6]));
    float2 p0 = cadd(t0, t2), p2 = cadd(t1, u3), p4 = csub(t0, t2), p6 = csub(t1, u3);
    t0 = cadd(z[1], z[5]); t1 = csub(z[1], z[5]);
    t2 = cadd(z[3], z[7]); u3 = cnegi(csub(z[3], z[7]));
    float2 p1 = cadd(t0, t2);
    float2 p3 = cmul(cadd(t1, u3), W1);
    float2 p5 = cnegi(csub(t0, t2));
    float2 p7 = cmul(csub(t1, u3), W3);
    z[0] = cadd(p0, p1); z[1] = csub(p0, p1);
    z[2] = cadd(p2, p3); z[3] = csub(p2, p3);
    z[4] = cadd(p4, p5); z[5] = csub(p4, p5);
    z[6] = cadd(p6, p7); z[7] = csub(p6, p7);
}

// inverse 8-pt head on registers
__device__ __forceinline__ void inv8(float2* z) {
    const float r = 0.70710678118654752f;
    const float2 W1c = make_float2(r, r);
    const float2 W3c = make_float2(-r, r);
    float2 q0 = cadd(z[0], z[1]), q1 = csub(z[0], z[1]);
    float2 q2 = cadd(z[2], z[3]), q3 = csub(z[2], z[3]);
    float2 q4 = cadd(z[4], z[5]), q5 = csub(z[4], z[5]);
    float2 q6 = cadd(z[6], z[7]), q7 = csub(z[6], z[7]);
    float2 t0 = cadd(q0, q4), t1 = csub(q0, q4);
    float2 t2 = cadd(q2, q6), v3 = cposi(csub(q2, q6));
    z[0] = cadd(t0, t2); z[2] = cadd(t1, v3); z[4] = csub(t0, t2); z[6] = csub(t1, v3);
    float2 b = cmul(q3, W1c);
    float2 c = cposi(q5);
    float2 d = cmul(q7, W3c);
    t0 = cadd(q1, c); t1 = csub(q1, c);
    t2 = cadd(b, d);  v3 = cposi(csub(b, d));
    z[1] = cadd(t0, t2); z[3] = cadd(t1, v3); z[5] = csub(t0, t2); z[7] = csub(t1, v3);
}

// ---------------- FFT of the 7 conjugated alpha rows ----------------
__global__ __launch_bounds__(512) void alphafft_kernel(const float* __restrict__ ar,
                                                       const float* __restrict__ ai) {
    __shared__ float2 sD[LFFT];
    const float2* __restrict__ stw = g_stw;
    int q = blockIdx.x, tid = threadIdx.x;

    float2 a = make_float2(ar[q * KW + tid], -ai[q * KW + tid]);
    float2 b = make_float2(0.f, 0.f);
    if (tid + 512 < KW) b = make_float2(ar[q * KW + tid + 512], -ai[q * KW + tid + 512]);
    float2 w  = stw[T512 + tid];
    float2 w2 = cmul(w, w);
    float2 w3 = cmul(w2, w);
    float2 t2 = b;
    float2 u3 = cnegi(b);
    sD[SW(tid)]        = cadd(a, t2);
    sD[SW(tid + 512)]  = cmul(cadd(a, u3), w);
    sD[SW(tid + 1024)] = cmul(csub(a, t2), w2);
    sD[SW(tid + 1536)] = cmul(csub(a, u3), w3);
    __syncthreads();
    r4_fwd<128, T128>(sD, stw, tid); __syncthreads();
    r4_fwd<32,  T32 >(sD, stw, tid); __syncthreads();
    r4_fwd<8,   T8  >(sD, stw, tid); __syncthreads();

    if (tid < 256) {
        float2 z[8];
#pragma unroll
        for (int c = 0; c < 8; c++) z[c] = sD[SW(8 * tid + c)];
        fwd8(z);
        float2* __restrict__ out = &g_B[q * LFFT + 8 * tid];
#pragma unroll
        for (int c = 0; c < 8; c++) {
            float2 v = z[c];
            out[c] = make_float2(v.x, -v.y);     // conj
        }
    }
}

// ---------------- G[n,f] = (1/L) sum_q e^{+2pi i n(q-3)/512} B[q,f] ----------------
#define GN_PER 8
__global__ __launch_bounds__(128) void gcomb_kernel() {
    int f  = blockIdx.x * 128 + threadIdx.x;
    int n0 = blockIdx.y * GN_PER;
    float2 Bq[7], p[7], st[7];
#pragma unroll
    for (int q = 0; q < 7; q++) {
        Bq[q] = g_B[q * LFFT + f];
        float qq = (float)(q - 3);
        float s, c;
        sincospif((float)n0 * qq * (1.0f / 256.0f), &s, &c);
        p[q] = make_float2(c, s);
        sincospif(qq * (1.0f / 256.0f), &s, &c);
        st[q] = make_float2(c, s);
    }
    float2* __restrict__ out = &g_G[n0 * LFFT + f];
#pragma unroll
    for (int n = 0; n < GN_PER; n++) {
        float gr = 0.f, gi = 0.f;
#pragma unroll
        for (int q = 0; q < 7; q++) {
            gr += p[q].x * Bq[q].x - p[q].y * Bq[q].y;
            gi += p[q].x * Bq[q].y + p[q].y * Bq[q].x;
        }
        out[(size_t)n * LFFT] = make_float2(gr * (1.0f / (float)LFFT), gi * (1.0f / (float)LFFT));
#pragma unroll
        for (int q = 0; q < 7; q++) p[q] = cmul(p[q], st[q]);
    }
}

// ---------------- STFT: 8 packed real-pair FFTs (16 frames = one t-chunk) per block ----------------
#define WSPAN (15 * HOPSZ + NFFT)   // 2432 samples per chunk
__global__ __launch_bounds__(512) void stft_kernel(const float* __restrict__ wav,
                                                   const float* __restrict__ win) {
    __shared__ float sRe[8 * NFFT];        // 8 FFT buffers
    __shared__ float sIm[8 * NFFT];
    __shared__ float2 sTw[256];
    __shared__ float sWav[WSPAN];
    __shared__ float sWin[NFFT];

    int chunk = blockIdx.x;                // 0..64
    int b     = blockIdx.y;
    int tid   = threadIdx.x;               // 512 threads
    int tf0   = chunk * TCH;               // first frame of chunk

    // stage twiddles, window, waveform span (reflect-padded)
    if (tid < 256) sTw[tid] = g_tw512[tid];
    if (tid < NFFT) sWin[tid] = win[tid];
    {
        int base = tf0 * HOPSZ - 256;
        const float* __restrict__ wb = wav + b * LSAMP;
#pragma unroll
        for (int k = 0; k < 5; k++) {
            int i = tid + k * 512;
            if (i < WSPAN) {
                int p = base + i;
                if (p < 0) p = -p;
                if (p >= LSAMP) p = 2 * LSAMP - 2 - p;
                sWav[i] = wb[p];
            }
        }
    }
    __syncthreads();

    // assemble 8 packed FFTs: FFT p = frame(tf0+2p) + i*frame(tf0+2p+1)
#pragma unroll
    for (int k = 0; k < 8; k++) {
        int o = tid + k * 512;             // o = p*512 + i
        int p = o >> 9, i = o & 511;
        float wv = sWin[i];
        sRe[o] = sWav[256 * p + i] * wv;
        sIm[o] = sWav[256 * p + 128 + i] * wv;
    }
    __syncthreads();

    // 9 radix-2 DIF stages, 2048 butterflies/stage over 8 FFTs, 4 per thread
    for (int s = 256; s >= 1; s >>= 1) {
        int mult = 256 / s;
#pragma unroll
        for (int rr = 0; rr < 4; rr++) {
            int g = tid + rr * 512;
            int f = g >> 8, u = g & 255;
            int j = u & (s - 1);
            int i0 = f * NFFT + ((u - j) << 1) + j;
            float2 w = sTw[j * mult];
            float arv = sRe[i0],     aiv = sIm[i0];
            float brv = sRe[i0 + s], biv = sIm[i0 + s];
            sRe[i0] = arv + brv;  sIm[i0] = aiv + biv;
            float dr = arv - brv, di = aiv - biv;
            sRe[i0 + s] = dr * w.x - di * w.y;
            sIm[i0 + s] = dr * w.y + di * w.x;
        }
        __syncthreads();
    }

    // unpack Hermitian pairs; write float4 = H[n][t_even], H[n][t_odd], coalesced
#pragma unroll
    for (int k = 0; k < 8; k++) {
        int o = tid + k * 512;             // o = n*8 + p
        int n = o >> 3, p = o & 7;
        int i = (int)(__brev((unsigned)n) >> 23);
        int m = (NFFT - n) & (NFFT - 1);
        int j = (int)(__brev((unsigned)m) >> 23);
        float Znr = sRe[p * NFFT + i], Zni = sIm[p * NFFT + i];
        float Zmr = sRe[p * NFFT + j], Zmi = sIm[p * NFFT + j];
        int te = tf0 + 2 * p;
        float4 hv;
        if (te <= 1024) {
            hv.x = 0.5f * (Znr + Zmr);  hv.y = 0.5f * (Zni - Zmi);
        } else { hv.x = 0.f; hv.y = 0.f; }
        if (te + 1 <= 1024) {
            hv.z = 0.5f * (Zni + Zmi);  hv.w = -0.5f * (Znr - Zmr);
        } else { hv.z = 0.f; hv.w = 0.f; }
        float4* __restrict__ dst =
            (float4*)&g_Ht[(((size_t)chunk * NROWS + b * NFFT + n) << 4) + 2 * p];
        *dst = hv;
    }
}

// ---------------- conv via radix-4 FFT: one (b,n) row per block ----------------
__global__ __launch_bounds__(512, 3) void conv_kernel() {
    __shared__ float2 sD[LFFT];
    __shared__ float warpsum[16];
    const float2* __restrict__ stw = g_stw;

    int row = blockIdx.x;
    int tid = threadIdx.x;

    // tiled H loads: t -> g_Ht[(t>>4)*NROWS + row][t&15]
    float2 a = g_Ht[(((tid >> 4) * NROWS + row) << 4) + (tid & 15)];
    float2 b = g_Ht[(((((tid + 512) >> 4)) * NROWS + row) << 4) + (tid & 15)];
    float2 c = (tid == 0) ? g_Ht[((64 * NROWS + row) << 4)] : make_float2(0.f, 0.f);
    {
        float2 w  = stw[T512 + tid];
        float2 w2 = cmul(w, w);
        float2 w3 = cmul(w2, w);
        float2 t0 = cadd(a, c), t1 = csub(a, c);
        float2 t2 = b,          u3 = cnegi(b);
        sD[SW(tid)]        = cadd(t0, t2);
        sD[SW(tid + 512)]  = cmul(cadd(t1, u3), w);
        sD[SW(tid + 1024)] = cmul(csub(t0, t2), w2);
        sD[SW(tid + 1536)] = cmul(csub(t1, u3), w3);
    }
    __syncthreads();
    r4_fwd<128, T128>(sD, stw, tid); __syncthreads();
    r4_fwd<32,  T32 >(sD, stw, tid); __syncthreads();
    r4_fwd<8,   T8  >(sD, stw, tid); __syncthreads();

    if (tid < 256) {
        float2 z[8];
#pragma unroll
        for (int cc = 0; cc < 8; cc++) z[cc] = sD[SW(8 * tid + cc)];
        fwd8(z);
        const float4* __restrict__ Gr =
            (const float4*)&g_G[(row & (NFFT - 1)) * LFFT + 8 * tid];
#pragma unroll
        for (int cc = 0; cc < 4; cc++) {
            float4 g = Gr[cc];
            float2 x0 = z[2 * cc], x1 = z[2 * cc + 1];
            z[2 * cc]     = make_float2(x0.x * g.x - x0.y * g.y, x0.x * g.y + x0.y * g.x);
            z[2 * cc + 1] = make_float2(x1.x * g.z - x1.y * g.w, x1.x * g.w + x1.y * g.z);
        }
        inv8(z);
#pragma unroll
        for (int cc = 0; cc < 8; cc++) sD[SW(8 * tid + cc)] = z[cc];
    }
    __syncthreads();
    r4_inv<8,   T8  >(sD, stw, tid); __syncthreads();
    r4_inv<32,  T32 >(sD, stw, tid); __syncthreads();
    r4_inv<128, T128>(sD, stw, tid); __syncthreads();

    float lsum;
    {
        float2 w = stw[T512 + tid];
        w.y = -w.y;
        float2 w2 = cmul(w, w);
        float2 w3 = cmul(w2, w);
        float2 ya = sD[SW(tid)];
        float2 yb = cmul(sD[SW(tid + 512)], w);
        float2 yc = cmul(sD[SW(tid + 1024)], w2);
        float2 yd = cmul(sD[SW(tid + 1536)], w3);
        float2 t0 = cadd(ya, yc), t1 = csub(ya, yc);
        float2 t2 = cadd(yb, yd), v3 = cposi(csub(yb, yd));
        float2 x0 = cadd(t0, t2);
        float2 x1 = cadd(t1, v3);
        float2 x3 = csub(t1, v3);
        lsum = x0.x * x0.x + x0.y * x0.y;
        if (tid < 2)  lsum += x1.x * x1.x + x1.y * x1.y;
        if (tid >= 1) lsum += x3.x * x3.x + x3.y * x3.y;
    }

#pragma unroll
    for (int off = 16; off > 0; off >>= 1)
        lsum += __shfl_down_sync(0xffffffff, lsum, off);
    if ((tid & 31) == 0) warpsum[tid >> 5] = lsum;
    __syncthreads();
    if (tid == 0) {
        float s = 0.f;
#pragma unroll
        for (int w = 0; w < 16; w++) s += warpsum[w];
        atomicAdd(&g_acc, (double)s);
    }
}

__global__ void finalize_kernel(float* out) {
    out[0] = (float)(g_acc / (double)(BATCH * TFRAMES));
}

extern "C" void kernel_launch(void* const* d_in, const int* in_sizes, int n_in,
                              void* d_out, int out_size) {
    const float* wav = (const float*)d_in[0];
    const float* win = (const float*)d_in[1];
    const float* ar  = (const float*)d_in[2];
    const float* ai  = (const float*)d_in[3];

    twinit_kernel<<<4, 256>>>();
    alphafft_kernel<<<7, 512>>>(ar, ai);
    dim3 gG(LFFT / 128, NFFT / GN_PER);
    gcomb_kernel<<<gG, 128>>>();
    dim3 gs(NCHUNK, BATCH);
    stft_kernel<<<gs, 512>>>(wav, win);
    conv_kernel<<<NROWS, 512>>>();
    finalize_kernel<<<1, 1>>>((float*)d_out);
}

// round 8
// speedup vs baseline: 8.1317x; 1.4294x over previous
#include <cuda_runtime.h>

#define NFFT    512
#define HOPSZ   128
#define BATCH   4
#define LSAMP   131072
#define TFRAMES 1025
#define KW      1023
#define NROWS   (BATCH * NFFT)   // 2048
#define LFFT    2048
#define TCH     16               // t per chunk in tiled H layout
#define NCHUNK  65               // 65*16 = 1040 >= 1025

// smem swizzle for 2048-pt conv FFT
#define SW(i) ((i) ^ (((((i) >> 5) & 7)) | ((((i) >> 5) & 3) << 3)))

// per-stage twiddle table offsets in g_stw
#define T512 0
#define T128 512
#define T32  640
#define T8   672
#define TWN  680

// ------------- device scratch (static, no allocs) -------------
__device__ float2 g_Ht[NCHUNK * NROWS * TCH];   // tiled: [chunk][row][16]
__device__ float2 g_B[7 * LFFT];
__device__ float2 g_G[NFFT * LFFT];
__device__ float2 g_tw512[256];                 // W_512^x = exp(-i pi x/256), x<256
__device__ float2 g_stw[TWN];
__device__ double g_acc;

__global__ void twinit_kernel() {
    int i = blockIdx.x * blockDim.x + threadIdx.x;
    if (i == 0) g_acc = 0.0;
    if (i < 256) {
        float s, c;
        sincospif(-(float)i * (1.0f / 256.0f), &s, &c);
        g_tw512[i] = make_float2(c, s);
    }
    if (i < TWN) {
        int j, M;
        if (i < T128)      { j = i;        M = 2048; }
        else if (i < T32)  { j = i - T128; M = 512;  }
        else if (i < T8)   { j = i - T32;  M = 128;  }
        else               { j = i - T8;   M = 32;   }
        float s, c;
        sincospif(-2.0f * (float)j / (float)M, &s, &c);
        g_stw[i] = make_float2(c, s);
    }
}

__device__ __forceinline__ float2 cmul(float2 a, float2 b) {
    return make_float2(a.x * b.x - a.y * b.y, a.x * b.y + a.y * b.x);
}
__device__ __forceinline__ float2 cadd(float2 a, float2 b) { return make_float2(a.x + b.x, a.y + b.y); }
__device__ __forceinline__ float2 csub(float2 a, float2 b) { return make_float2(a.x - b.x, a.y - b.y); }
__device__ __forceinline__ float2 cnegi(float2 a) { return make_float2(a.y, -a.x); }   // -i*a
__device__ __forceinline__ float2 cposi(float2 a) { return make_float2(-a.y, a.x); }   // +i*a

template<int S, int TOFF>
__device__ __forceinline__ void r4_fwd(float2* sD, const float2* __restrict__ stw, int tid) {
    int j  = tid & (S - 1);
    int i0 = ((tid - j) << 2) + j;
    float2 w  = stw[TOFF + j];
    float2 w2 = cmul(w, w);
    float2 w3 = cmul(w2, w);
    float2 a = sD[SW(i0)], b = sD[SW(i0 + S)], c = sD[SW(i0 + 2 * S)], d = sD[SW(i0 + 3 * S)];
    float2 t0 = cadd(a, c), t1 = csub(a, c);
    float2 t2 = cadd(b, d), u3 = cnegi(csub(b, d));
    sD[SW(i0)]         = cadd(t0, t2);
    sD[SW(i0 + S)]     = cmul(cadd(t1, u3), w);
    sD[SW(i0 + 2 * S)] = cmul(csub(t0, t2), w2);
    sD[SW(i0 + 3 * S)] = cmul(csub(t1, u3), w3);
}

template<int S, int TOFF>
__device__ __forceinline__ void r4_inv(float2* sD, const float2* __restrict__ stw, int tid) {
    int j  = tid & (S - 1);
    int i0 = ((tid - j) << 2) + j;
    float2 w = stw[TOFF + j];
    w.y = -w.y;
    float2 w2 = cmul(w, w);
    float2 w3 = cmul(w2, w);
    float2 a = sD[SW(i0)];
    float2 b = cmul(sD[SW(i0 + S)], w);
    float2 c = cmul(sD[SW(i0 + 2 * S)], w2);
    float2 d = cmul(sD[SW(i0 + 3 * S)], w3);
    float2 t0 = cadd(a, c), t1 = csub(a, c);
    float2 t2 = cadd(b, d), v3 = cposi(csub(b, d));
    sD[SW(i0)]         = cadd(t0, t2);
    sD[SW(i0 + S)]     = cadd(t1, v3);
    sD[SW(i0 + 2 * S)] = csub(t0, t2);
    sD[SW(i0 + 3 * S)] = csub(t1, v3);
}

// 8-pt DFT on registers (DIF radix-4 + radix-2). Output at reg p = bin binOf[p],
// binOf = {0,4,1,5,2,6,3,7};  posOf[m] = {0,2,4,6,1,3,5,7}.
__device__ __forceinline__ void fwd8(float2* z) {
    const float r = 0.70710678118654752f;
    const float2 W1 = make_float2(r, -r);
    const float2 W3 = make_float2(-r, -r);
    float2 t0 = cadd(z[0], z[4]), t1 = csub(z[0], z[4]);
    float2 t2 = cadd(z[2], z[6]), u3 = cnegi(csub(z[2], z[6]));
    float2 p0 = cadd(t0, t2), p2 = cadd(t1, u3), p4 = csub(t0, t2), p6 = csub(t1, u3);
    t0 = cadd(z[1], z[5]); t1 = csub(z[1], z[5]);
    t2 = cadd(z[3], z[7]); u3 = cnegi(csub(z[3], z[7]));
    float2 p1 = cadd(t0, t2);
    float2 p3 = cmul(cadd(t1, u3), W1);
    float2 p5 = cnegi(csub(t0, t2));
    float2 p7 = cmul(csub(t1, u3), W3);
    z[0] = cadd(p0, p1); z[1] = csub(p0, p1);
    z[2] = cadd(p2, p3); z[3] = csub(p2, p3);
    z[4] = cadd(p4, p5); z[5] = csub(p4, p5);
    z[6] = cadd(p6, p7); z[7] = csub(p6, p7);
}

__device__ __forceinline__ void inv8(float2* z) {
    const float r = 0.70710678118654752f;
    const float2 W1c = make_float2(r, r);
    const float2 W3c = make_float2(-r, r);
    float2 q0 = cadd(z[0], z[1]), q1 = csub(z[0], z[1]);
    float2 q2 = cadd(z[2], z[3]), q3 = csub(z[2], z[3]);
    float2 q4 = cadd(z[4], z[5]), q5 = csub(z[4], z[5]);
    float2 q6 = cadd(z[6], z[7]), q7 = csub(z[6], z[7]);
    float2 t0 = cadd(q0, q4), t1 = csub(q0, q4);
    float2 t2 = cadd(q2, q6), v3 = cposi(csub(q2, q6));
    z[0] = cadd(t0, t2); z[2] = cadd(t1, v3); z[4] = csub(t0, t2); z[6] = csub(t1, v3);
    float2 b = cmul(q3, W1c);
    float2 c = cposi(q5);
    float2 d = cmul(q7, W3c);
    t0 = cadd(q1, c); t1 = csub(q1, c);
    t2 = cadd(b, d);  v3 = cposi(csub(b, d));
    z[1] = cadd(t0, t2); z[3] = cadd(t1, v3); z[5] = csub(t0, t2); z[7] = csub(t1, v3);
}

// apply twiddles w1^bin to fwd8 outputs, in bin order via posOf
__device__ __forceinline__ void twiddle_chain(float2* z, float2 w1) {
    const int posOf[8] = {0, 2, 4, 6, 1, 3, 5, 7};
    float2 wm = w1;
    z[posOf[1]] = cmul(z[posOf[1]], wm);
#pragma unroll
    for (int m = 2; m < 8; m++) {
        wm = cmul(wm, w1);
        z[posOf[m]] = cmul(z[posOf[m]], wm);
    }
}

// ---------------- FFT of the 7 conjugated alpha rows ----------------
__global__ __launch_bounds__(512) void alphafft_kernel(const float* __restrict__ ar,
                                                       const float* __restrict__ ai) {
    __shared__ float2 sD[LFFT];
    const float2* __restrict__ stw = g_stw;
    int q = blockIdx.x, tid = threadIdx.x;

    float2 a = make_float2(ar[q * KW + tid], -ai[q * KW + tid]);
    float2 b = make_float2(0.f, 0.f);
    if (tid + 512 < KW) b = make_float2(ar[q * KW + tid + 512], -ai[q * KW + tid + 512]);
    float2 w  = stw[T512 + tid];
    float2 w2 = cmul(w, w);
    float2 w3 = cmul(w2, w);
    float2 t2 = b;
    float2 u3 = cnegi(b);
    sD[SW(tid)]        = cadd(a, t2);
    sD[SW(tid + 512)]  = cmul(cadd(a, u3), w);
    sD[SW(tid + 1024)] = cmul(csub(a, t2), w2);
    sD[SW(tid + 1536)] = cmul(csub(a, u3), w3);
    __syncthreads();
    r4_fwd<128, T128>(sD, stw, tid); __syncthreads();
    r4_fwd<32,  T32 >(sD, stw, tid); __syncthreads();
    r4_fwd<8,   T8  >(sD, stw, tid); __syncthreads();

    if (tid < 256) {
        float2 z[8];
#pragma unroll
        for (int c = 0; c < 8; c++) z[c] = sD[SW(8 * tid + c)];
        fwd8(z);
        float2* __restrict__ out = &g_B[q * LFFT + 8 * tid];
#pragma unroll
        for (int c = 0; c < 8; c++) {
            float2 v = z[c];
            out[c] = make_float2(v.x, -v.y);
        }
    }
}

// ---------------- G[n,f] ----------------
#define GN_PER 8
__global__ __launch_bounds__(128) void gcomb_kernel() {
    int f  = blockIdx.x * 128 + threadIdx.x;
    int n0 = blockIdx.y * GN_PER;
    float2 Bq[7], p[7], st[7];
#pragma unroll
    for (int q = 0; q < 7; q++) {
        Bq[q] = g_B[q * LFFT + f];
        float qq = (float)(q - 3);
        float s, c;
        sincospif((float)n0 * qq * (1.0f / 256.0f), &s, &c);
        p[q] = make_float2(c, s);
        sincospif(qq * (1.0f / 256.0f), &s, &c);
        st[q] = make_float2(c, s);
    }
    float2* __restrict__ out = &g_G[n0 * LFFT + f];
#pragma unroll
    for (int n = 0; n < GN_PER; n++) {
        float gr = 0.f, gi = 0.f;
#pragma unroll
        for (int q = 0; q < 7; q++) {
            gr += p[q].x * Bq[q].x - p[q].y * Bq[q].y;
            gi += p[q].x * Bq[q].y + p[q].y * Bq[q].x;
        }
        out[(size_t)n * LFFT] = make_float2(gr * (1.0f / (float)LFFT), gi * (1.0f / (float)LFFT));
#pragma unroll
        for (int q = 0; q < 7; q++) p[q] = cmul(p[q], st[q]);
    }
}

// ---------------- STFT: register radix-8 (8x8x8), 8 packed FFTs per block ----------------
#define WSPAN (15 * HOPSZ + NFFT)   // 2432
#define SST   584                   // per-FFT smem stride (conflict-free layouts)
__global__ __launch_bounds__(512) void stft_kernel(const float* __restrict__ wav,
                                                   const float* __restrict__ win) {
    __shared__ float sRe[8 * SST];
    __shared__ float sIm[8 * SST];
    __shared__ float sWav[WSPAN];
    __shared__ float sWin[NFFT];

    int chunk = blockIdx.x;                // 0..64
    int b     = blockIdx.y;
    int tid   = threadIdx.x;               // 512
    int tf0   = chunk * TCH;
    int f     = tid >> 6;                  // FFT index 0..7 (frames tf0+2f, tf0+2f+1)
    int j     = tid & 63;

    // stage window + waveform span (reflect-padded)
    if (tid < NFFT) sWin[tid] = win[tid];
    {
        int base = tf0 * HOPSZ - 256;
        const float* __restrict__ wb = wav + b * LSAMP;
#pragma unroll
        for (int k = 0; k < 5; k++) {
            int i = tid + k * 512;
            if (i < WSPAN) {
                int p = base + i;
                if (p < 0) p = -p;
                if (p >= LSAMP) p = 2 * LSAMP - 2 - p;
                sWav[i] = wb[p];
            }
        }
    }
    __syncthreads();

    float* fRe = &sRe[f * SST];
    float* fIm = &sIm[f * SST];
    float2 z[8];

    // load x[j + 64u] (packed pair of real frames), stage A DFT-8 + twiddle W_512^(j*m)
#pragma unroll
    for (int u = 0; u < 8; u++) {
        int i = j + 64 * u;
        float wv = sWin[i];
        z[u] = make_float2(sWav[256 * f + i] * wv, sWav[256 * f + 128 + i] * wv);
    }
    fwd8(z);
    twiddle_chain(z, g_tw512[j]);
    // write ex1: addr = bin*72 + j   (binOf[p] = {0,4,1,5,2,6,3,7})
    {
        const int binOf[8] = {0, 4, 1, 5, 2, 6, 3, 7};
#pragma unroll
        for (int p = 0; p < 8; p++) {
            fRe[binOf[p] * 72 + j] = z[p].x;
            fIm[binOf[p] * 72 + j] = z[p].y;
        }
    }
    __syncthreads();

    // stage B: thread (m = j>>3, j0 = j&7): read ex1[m*72 + j0 + 8u]
    {
        int m = j >> 3, j0 = j & 7;
#pragma unroll
        for (int u = 0; u < 8; u++) {
            int a = m * 72 + j0 + 8 * u;
            z[u] = make_float2(fRe[a], fIm[a]);
        }
        fwd8(z);
        twiddle_chain(z, g_tw512[8 * j0]);
        __syncthreads();
        // write ex2: addr = (m*8 + bin)*9 + j0
        const int binOf[8] = {0, 4, 1, 5, 2, 6, 3, 7};
#pragma unroll
        for (int p = 0; p < 8; p++) {
            int a = (m * 8 + binOf[p]) * 9 + j0;
            fRe[a] = z[p].x;
            fIm[a] = z[p].y;
        }
    }
    __syncthreads();

    // stage C: thread j handles (m = j>>3, mB = j&7): read ex2[j*9 + u]
    {
#pragma unroll
        for (int u = 0; u < 8; u++) {
            int a = j * 9 + u;
            z[u] = make_float2(fRe[a], fIm[a]);
        }
        fwd8(z);
        __syncthreads();
        // write natural-order spectrum: bin n = m + 8*mB + 64*binOf[p]
        const int binOf[8] = {0, 4, 1, 5, 2, 6, 3, 7};
        int m = j >> 3, mB = j & 7;
#pragma unroll
        for (int p = 0; p < 8; p++) {
            int n = m + 8 * mB + 64 * binOf[p];
            fRe[n] = z[p].x;
            fIm[n] = z[p].y;
        }
    }
    __syncthreads();

    // Hermitian unpack; coalesced float4 writes into tiled H
#pragma unroll
    for (int k = 0; k < 8; k++) {
        int o = tid + k * 512;             // o = n*8 + p
        int n = o >> 3, p = o & 7;
        int m512 = (NFFT - n) & (NFFT - 1);
        float Znr = sRe[p * SST + n],    Zni = sIm[p * SST + n];
        float Zmr = sRe[p * SST + m512], Zmi = sIm[p * SST + m512];
        int te = tf0 + 2 * p;
        float4 hv;
        if (te <= 1024) {
            hv.x = 0.5f * (Znr + Zmr);  hv.y = 0.5f * (Zni - Zmi);
        } else { hv.x = 0.f; hv.y = 0.f; }
        if (te + 1 <= 1024) {
            hv.z = 0.5f * (Zni + Zmi);  hv.w = -0.5f * (Znr - Zmr);
        } else { hv.z = 0.f; hv.w = 0.f; }
        float4* __restrict__ dst =
            (float4*)&g_Ht[(((size_t)chunk * NROWS + b * NFFT + n) << 4) + 2 * p];
        *dst = hv;
    }
}

// ---------------- conv via radix-4 FFT: one (b,n) row per block ----------------
__global__ __launch_bounds__(512, 3) void conv_kernel() {
    __shared__ float2 sD[LFFT];
    __shared__ float warpsum[16];
    const float2* __restrict__ stw = g_stw;

    int row = blockIdx.x;
    int tid = threadIdx.x;

    float2 a = g_Ht[(((tid >> 4) * NROWS + row) << 4) + (tid & 15)];
    float2 b = g_Ht[(((((tid + 512) >> 4)) * NROWS + row) << 4) + (tid & 15)];
    float2 c = (tid == 0) ? g_Ht[((64 * NROWS + row) << 4)] : make_float2(0.f, 0.f);
    {
        float2 w  = stw[T512 + tid];
        float2 w2 = cmul(w, w);
        float2 w3 = cmul(w2, w);
        float2 t0 = cadd(a, c), t1 = csub(a, c);
        float2 t2 = b,          u3 = cnegi(b);
        sD[SW(tid)]        = cadd(t0, t2);
        sD[SW(tid + 512)]  = cmul(cadd(t1, u3), w);
        sD[SW(tid + 1024)] = cmul(csub(t0, t2), w2);
        sD[SW(tid + 1536)] = cmul(csub(t1, u3), w3);
    }
    __syncthreads();
    r4_fwd<128, T128>(sD, stw, tid); __syncthreads();
    r4_fwd<32,  T32 >(sD, stw, tid); __syncthreads();
    r4_fwd<8,   T8  >(sD, stw, tid); __syncthreads();

    if (tid < 256) {
        float2 z[8];
#pragma unroll
        for (int cc = 0; cc < 8; cc++) z[cc] = sD[SW(8 * tid + cc)];
        fwd8(z);
        const float4* __restrict__ Gr =
            (const float4*)&g_G[(row & (NFFT - 1)) * LFFT + 8 * tid];
#pragma unroll
        for (int cc = 0; cc < 4; cc++) {
            float4 g = Gr[cc];
            float2 x0 = z[2 * cc], x1 = z[2 * cc + 1];
            z[2 * cc]     = make_float2(x0.x * g.x - x0.y * g.y, x0.x * g.y + x0.y * g.x);
            z[2 * cc + 1] = make_float2(x1.x * g.z - x1.y * g.w, x1.x * g.w + x1.y * g.z);
        }
        inv8(z);
#pragma unroll
        for (int cc = 0; cc < 8; cc++) sD[SW(8 * tid + cc)] = z[cc];
    }
    __syncthreads();
    r4_inv<8,   T8  >(sD, stw, tid); __syncthreads();
    r4_inv<32,  T32 >(sD, stw, tid); __syncthreads();
    r4_inv<128, T128>(sD, stw, tid); __syncthreads();

    float lsum;
    {
        float2 w = stw[T512 + tid];
        w.y = -w.y;
        float2 w2 = cmul(w, w);
        float2 w3 = cmul(w2, w);
        float2 ya = sD[SW(tid)];
        float2 yb = cmul(sD[SW(tid + 512)], w);
        float2 yc = cmul(sD[SW(tid + 1024)], w2);
        float2 yd = cmul(sD[SW(tid + 1536)], w3);
        float2 t0 = cadd(ya, yc), t1 = csub(ya, yc);
        float2 t2 = cadd(yb, yd), v3 = cposi(csub(yb, yd));
        float2 x0 = cadd(t0, t2);
        float2 x1 = cadd(t1, v3);
        float2 x3 = csub(t1, v3);
        lsum = x0.x * x0.x + x0.y * x0.y;
        if (tid < 2)  lsum += x1.x * x1.x + x1.y * x1.y;
        if (tid >= 1) lsum += x3.x * x3.x + x3.y * x3.y;
    }

#pragma unroll
    for (int off = 16; off > 0; off >>= 1)
        lsum += __shfl_down_sync(0xffffffff, lsum, off);
    if ((tid & 31) == 0) warpsum[tid >> 5] = lsum;
    __syncthreads();
    if (tid == 0) {
        float s = 0.f;
#pragma unroll
        for (int w = 0; w < 16; w++) s += warpsum[w];
        atomicAdd(&g_acc, (double)s);
    }
}

__global__ void finalize_kernel(float* out) {
    out[0] = (float)(g_acc / (double)(BATCH * TFRAMES));
}

extern "C" void kernel_launch(void* const* d_in, const int* in_sizes, int n_in,
                              void* d_out, int out_size) {
    const float* wav = (const float*)d_in[0];
    const float* win = (const float*)d_in[1];
    const float* ar  = (const float*)d_in[2];
    const float* ai  = (const float*)d_in[3];

    twinit_kernel<<<4, 256>>>();
    alphafft_kernel<<<7, 512>>>(ar, ai);
    dim3 gG(LFFT / 128, NFFT / GN_PER);
    gcomb_kernel<<<gG, 128>>>();
    dim3 gs(NCHUNK, BATCH);
    stft_kernel<<<gs, 512>>>(wav, win);
    conv_kernel<<<NROWS, 512>>>();
    finalize_kernel<<<1, 1>>>((float*)d_out);
}

// round 9
// speedup vs baseline: 8.8450x; 1.0877x over previous
#include <cuda_runtime.h>

#define NFFT    512
#define HOPSZ   128
#define BATCH   4
#define LSAMP   131072
#define TFRAMES 1025
#define KW      1023
#define NROWS   (BATCH * NFFT)   // 2048
#define LFFT    2048
#define TCH     16
#define NCHUNK  65

// per-stage twiddle table offsets in g_stw (only T512 used now; others kept for stft-free init)
#define T512 0
#define T128 512
#define T32  640
#define T8   672
#define TWN  680

// exchange region size (floats): max(8*264+256, 64*36+32) = 2304
#define XR 2304

// ------------- device scratch (static, no allocs) -------------
__device__ float2 g_Ht[NCHUNK * NROWS * TCH];   // tiled: [chunk][row][16]
__device__ float2 g_B[7 * LFFT];                // scrambled order (t*8+p)
__device__ float2 g_G[NFFT * LFFT];             // scrambled order
__device__ float2 g_tw512[256];                 // W_512^x for stft
__device__ float2 g_stw[TWN];                   // W_2048^j at T512 (+legacy)
__device__ double g_acc;

__global__ void twinit_kernel() {
    int i = blockIdx.x * blockDim.x + threadIdx.x;
    if (i == 0) g_acc = 0.0;
    if (i < 256) {
        float s, c;
        sincospif(-(float)i * (1.0f / 256.0f), &s, &c);
        g_tw512[i] = make_float2(c, s);
    }
    if (i < TWN) {
        int j, M;
        if (i < T128)      { j = i;        M = 2048; }
        else if (i < T32)  { j = i - T128; M = 512;  }
        else if (i < T8)   { j = i - T32;  M = 128;  }
        else               { j = i - T8;   M = 32;   }
        float s, c;
        sincospif(-2.0f * (float)j / (float)M, &s, &c);
        g_stw[i] = make_float2(c, s);
    }
}

__device__ __forceinline__ float2 cmul(float2 a, float2 b) {
    return make_float2(a.x * b.x - a.y * b.y, a.x * b.y + a.y * b.x);
}
__device__ __forceinline__ float2 cadd(float2 a, float2 b) { return make_float2(a.x + b.x, a.y + b.y); }
__device__ __forceinline__ float2 csub(float2 a, float2 b) { return make_float2(a.x - b.x, a.y - b.y); }
__device__ __forceinline__ float2 cnegi(float2 a) { return make_float2(a.y, -a.x); }   // -i*a
__device__ __forceinline__ float2 cposi(float2 a) { return make_float2(-a.y, a.x); }   // +i*a

// 8-pt DFT on registers; reg p holds bin binOf[p], binOf={0,4,1,5,2,6,3,7}, posOf={0,2,4,6,1,3,5,7}
__device__ __forceinline__ void fwd8(float2* z) {
    const float r = 0.70710678118654752f;
    const float2 W1 = make_float2(r, -r);
    const float2 W3 = make_float2(-r, -r);
    float2 t0 = cadd(z[0], z[4]), t1 = csub(z[0], z[4]);
    float2 t2 = cadd(z[2], z[6]), u3 = cnegi(csub(z[2], z[6]));
    float2 p0 = cadd(t0, t2), p2 = cadd(t1, u3), p4 = csub(t0, t2), p6 = csub(t1, u3);
    t0 = cadd(z[1], z[5]); t1 = csub(z[1], z[5]);
    t2 = cadd(z[3], z[7]); u3 = cnegi(csub(z[3], z[7]));
    float2 p1 = cadd(t0, t2);
    float2 p3 = cmul(cadd(t1, u3), W1);
    float2 p5 = cnegi(csub(t0, t2));
    float2 p7 = cmul(csub(t1, u3), W3);
    z[0] = cadd(p0, p1); z[1] = csub(p0, p1);
    z[2] = cadd(p2, p3); z[3] = csub(p2, p3);
    z[4] = cadd(p4, p5); z[5] = csub(p4, p5);
    z[6] = cadd(p6, p7); z[7] = csub(p6, p7);
}

// inverse: input in binOf layout, output natural j order (unnormalized x8)
__device__ __forceinline__ void inv8(float2* z) {
    const float r = 0.70710678118654752f;
    const float2 W1c = make_float2(r, r);
    const float2 W3c = make_float2(-r, r);
    float2 q0 = cadd(z[0], z[1]), q1 = csub(z[0], z[1]);
    float2 q2 = cadd(z[2], z[3]), q3 = csub(z[2], z[3]);
    float2 q4 = cadd(z[4], z[5]), q5 = csub(z[4], z[5]);
    float2 q6 = cadd(z[6], z[7]), q7 = csub(z[6], z[7]);
    float2 t0 = cadd(q0, q4), t1 = csub(q0, q4);
    float2 t2 = cadd(q2, q6), v3 = cposi(csub(q2, q6));
    z[0] = cadd(t0, t2); z[2] = cadd(t1, v3); z[4] = csub(t0, t2); z[6] = csub(t1, v3);
    float2 b = cmul(q3, W1c);
    float2 c = cposi(q5);
    float2 d = cmul(q7, W3c);
    t0 = cadd(q1, c); t1 = csub(q1, c);
    t2 = cadd(b, d);  v3 = cposi(csub(b, d));
    z[1] = cadd(t0, t2); z[3] = cadd(t1, v3); z[5] = csub(t0, t2); z[7] = csub(t1, v3);
}

// multiply bin m by w1^m (regs in binOf layout)
__device__ __forceinline__ void twiddle_chain(float2* z, float2 w1) {
    const int posOf[8] = {0, 2, 4, 6, 1, 3, 5, 7};
    float2 wm = w1;
    z[posOf[1]] = cmul(z[posOf[1]], wm);
#pragma unroll
    for (int m = 2; m < 8; m++) {
        wm = cmul(wm, w1);
        z[posOf[m]] = cmul(z[posOf[m]], wm);
    }
}

__device__ __forceinline__ float2 shflx(float2 v, int m) {
    return make_float2(__shfl_xor_sync(0xffffffffu, v.x, m),
                       __shfl_xor_sync(0xffffffffu, v.y, m));
}

// distributed 4-pt DFT across lanes l=j2 (lane&3); lane ends with bin b4={0,2,1,3}
__device__ __forceinline__ void fwd4sh(float2* z, int l) {
#pragma unroll
    for (int p = 0; p < 8; p++) {
        float2 v = z[p];
        float2 q = shflx(v, 2);
        v = (l & 2) ? csub(q, v) : cadd(v, q);
        if (l == 3) v = cnegi(v);
        q = shflx(v, 1);
        v = (l & 1) ? csub(q, v) : cadd(v, q);
        z[p] = v;
    }
}

__device__ __forceinline__ void inv4sh(float2* z, int l) {
#pragma unroll
    for (int p = 0; p < 8; p++) {
        float2 v = z[p];
        float2 q = shflx(v, 1);
        v = (l & 1) ? csub(q, v) : cadd(v, q);
        if (l == 3) v = cposi(v);
        q = shflx(v, 2);
        v = (l & 2) ? csub(q, v) : cadd(v, q);
        z[p] = v;
    }
}

// ---- shared forward 2048-pt path (stages A,B,C + shfl4); leaves spectrum in z (thread t, regs p) ----
// sReX/sImX are two XR-float regions.
__device__ __forceinline__ void fft2048_fwd_reg(
    float2* z, float* sRe1, float* sIm1, float* sRe2, float* sIm2, int t)
{
    // stage A: z[u] preloaded by caller; twiddle W_2048^t
    fwd8(z);
    twiddle_chain(z, g_stw[T512 + t]);
    {
        const int binOf[8] = {0, 4, 1, 5, 2, 6, 3, 7};
#pragma unroll
        for (int p = 0; p < 8; p++) {
            int a = binOf[p] * 264 + t;
            sRe1[a] = z[p].x; sIm1[a] = z[p].y;
        }
    }
    __syncthreads();

    // stage B: mA = t>>5, j1 = t&31
    {
        int mA = t >> 5, j1 = t & 31;
#pragma unroll
        for (int v = 0; v < 8; v++) {
            int a = mA * 264 + j1 + 32 * v;
            z[v] = make_float2(sRe1[a], sIm1[a]);
        }
        fwd8(z);
        float sw, cw;
        sincospif(-(float)j1 * (1.0f / 128.0f), &sw, &cw);
        twiddle_chain(z, make_float2(cw, sw));
        const int binOf[8] = {0, 4, 1, 5, 2, 6, 3, 7};
#pragma unroll
        for (int p = 0; p < 8; p++) {
            int a = (mA * 8 + binOf[p]) * 36 + j1;
            sRe2[a] = z[p].x; sIm2[a] = z[p].y;
        }
    }
    __syncthreads();

    // stage C: g = t>>2, j2 = t&3
    {
        int g = t >> 2, j2 = t & 3;
#pragma unroll
        for (int w = 0; w < 8; w++) {
            int a = g * 36 + j2 + 4 * w;
            z[w] = make_float2(sRe2[a], sIm2[a]);
        }
        fwd8(z);
        float sw, cw;
        sincospif(-(float)j2 * (1.0f / 16.0f), &sw, &cw);
        twiddle_chain(z, make_float2(cw, sw));
        fwd4sh(z, j2);
    }
}

// ---------------- FFT of the 7 conjugated alpha rows (new structure) ----------------
__global__ __launch_bounds__(256) void alphafft_kernel(const float* __restrict__ ar,
                                                       const float* __restrict__ ai) {
    __shared__ float sRe1[XR], sIm1[XR], sRe2[XR], sIm2[XR];
    int q = blockIdx.x, t = threadIdx.x;

    float2 z[8];
#pragma unroll
    for (int u = 0; u < 8; u++) {
        int i = t + 256 * u;
        if (u <= 2 || (u == 3 && t < 255))
            z[u] = make_float2(ar[q * KW + i], -ai[q * KW + i]);
        else
            z[u] = make_float2(0.f, 0.f);
    }
    fft2048_fwd_reg(z, sRe1, sIm1, sRe2, sIm2, t);

    float2* __restrict__ out = &g_B[q * LFFT + t * 8];
#pragma unroll
    for (int p = 0; p < 8; p++)
        out[p] = make_float2(z[p].x, -z[p].y);   // conj
}

// ---------------- G[n,f] (pointwise in scrambled f; unchanged math) ----------------
#define GN_PER 8
__global__ __launch_bounds__(128) void gcomb_kernel() {
    int f  = blockIdx.x * 128 + threadIdx.x;
    int n0 = blockIdx.y * GN_PER;
    float2 Bq[7], p[7], st[7];
#pragma unroll
    for (int q = 0; q < 7; q++) {
        Bq[q] = g_B[q * LFFT + f];
        float qq = (float)(q - 3);
        float s, c;
        sincospif((float)n0 * qq * (1.0f / 256.0f), &s, &c);
        p[q] = make_float2(c, s);
        sincospif(qq * (1.0f / 256.0f), &s, &c);
        st[q] = make_float2(c, s);
    }
    float2* __restrict__ out = &g_G[n0 * LFFT + f];
#pragma unroll
    for (int n = 0; n < GN_PER; n++) {
        float gr = 0.f, gi = 0.f;
#pragma unroll
        for (int q = 0; q < 7; q++) {
            gr += p[q].x * Bq[q].x - p[q].y * Bq[q].y;
            gi += p[q].x * Bq[q].y + p[q].y * Bq[q].x;
        }
        out[(size_t)n * LFFT] = make_float2(gr * (1.0f / (float)LFFT), gi * (1.0f / (float)LFFT));
#pragma unroll
        for (int q = 0; q < 7; q++) p[q] = cmul(p[q], st[q]);
    }
}

// ---------------- STFT: register radix-8 (unchanged from R7) ----------------
#define WSPAN (15 * HOPSZ + NFFT)   // 2432
#define SST   584
__global__ __launch_bounds__(512) void stft_kernel(const float* __restrict__ wav,
                                                   const float* __restrict__ win) {
    __shared__ float sRe[8 * SST];
    __shared__ float sIm[8 * SST];
    __shared__ float sWav[WSPAN];
    __shared__ float sWin[NFFT];

    int chunk = blockIdx.x;
    int b     = blockIdx.y;
    int tid   = threadIdx.x;
    int tf0   = chunk * TCH;
    int f     = tid >> 6;
    int j     = tid & 63;

    if (tid < NFFT) sWin[tid] = win[tid];
    {
        int base = tf0 * HOPSZ - 256;
        const float* __restrict__ wb = wav + b * LSAMP;
#pragma unroll
        for (int k = 0; k < 5; k++) {
            int i = tid + k * 512;
            if (i < WSPAN) {
                int p = base + i;
                if (p < 0) p = -p;
                if (p >= LSAMP) p = 2 * LSAMP - 2 - p;
                sWav[i] = wb[p];
            }
        }
    }
    __syncthreads();

    float* fRe = &sRe[f * SST];
    float* fIm = &sIm[f * SST];
    float2 z[8];

#pragma unroll
    for (int u = 0; u < 8; u++) {
        int i = j + 64 * u;
        float wv = sWin[i];
        z[u] = make_float2(sWav[256 * f + i] * wv, sWav[256 * f + 128 + i] * wv);
    }
    fwd8(z);
    twiddle_chain(z, g_tw512[j]);
    {
        const int binOf[8] = {0, 4, 1, 5, 2, 6, 3, 7};
#pragma unroll
        for (int p = 0; p < 8; p++) {
            fRe[binOf[p] * 72 + j] = z[p].x;
            fIm[binOf[p] * 72 + j] = z[p].y;
        }
    }
    __syncthreads();

    {
        int m = j >> 3, j0 = j & 7;
#pragma unroll
        for (int u = 0; u < 8; u++) {
            int a = m * 72 + j0 + 8 * u;
            z[u] = make_float2(fRe[a], fIm[a]);
        }
        fwd8(z);
        twiddle_chain(z, g_tw512[8 * j0]);
        __syncthreads();
        const int binOf[8] = {0, 4, 1, 5, 2, 6, 3, 7};
#pragma unroll
        for (int p = 0; p < 8; p++) {
            int a = (m * 8 + binOf[p]) * 9 + j0;
            fRe[a] = z[p].x;
            fIm[a] = z[p].y;
        }
    }
    __syncthreads();

    {
#pragma unroll
        for (int u = 0; u < 8; u++) {
            int a = j * 9 + u;
            z[u] = make_float2(fRe[a], fIm[a]);
        }
        fwd8(z);
        __syncthreads();
        const int binOf[8] = {0, 4, 1, 5, 2, 6, 3, 7};
        int m = j >> 3, mB = j & 7;
#pragma unroll
        for (int p = 0; p < 8; p++) {
            int n = m + 8 * mB + 64 * binOf[p];
            fRe[n] = z[p].x;
            fIm[n] = z[p].y;
        }
    }
    __syncthreads();

#pragma unroll
    for (int k = 0; k < 8; k++) {
        int o = tid + k * 512;
        int n = o >> 3, p = o & 7;
        int m512 = (NFFT - n) & (NFFT - 1);
        float Znr = sRe[p * SST + n],    Zni = sIm[p * SST + n];
        float Zmr = sRe[p * SST + m512], Zmi = sIm[p * SST + m512];
        int te = tf0 + 2 * p;
        float4 hv;
        if (te <= 1024) {
            hv.x = 0.5f * (Znr + Zmr);  hv.y = 0.5f * (Zni - Zmi);
        } else { hv.x = 0.f; hv.y = 0.f; }
        if (te + 1 <= 1024) {
            hv.z = 0.5f * (Zni + Zmi);  hv.w = -0.5f * (Znr - Zmr);
        } else { hv.z = 0.f; hv.w = 0.f; }
        float4* __restrict__ dst =
            (float4*)&g_Ht[(((size_t)chunk * NROWS + b * NFFT + n) << 4) + 2 * p];
        *dst = hv;
    }
}

// ---------------- conv: register radix 8-8-8-4, one row per 256-thread block ----------------
__global__ __launch_bounds__(256, 4) void conv_kernel() {
    __shared__ float sRe1[XR], sIm1[XR], sRe2[XR], sIm2[XR];
    __shared__ float warpsum[8];

    int row = blockIdx.x;
    int t   = threadIdx.x;

    // load x[i], i = t + 256u, from tiled g_Ht (H[t] for t<=1024, else 0)
    float2 z[8];
#pragma unroll
    for (int u = 0; u < 4; u++) {
        int i = t + 256 * u;
        z[u] = g_Ht[(((i >> 4) * NROWS + row) << 4) + (i & 15)];
    }
    z[4] = (t == 0) ? g_Ht[((64 * NROWS + row) << 4)] : make_float2(0.f, 0.f);
    z[5] = make_float2(0.f, 0.f);
    z[6] = make_float2(0.f, 0.f);
    z[7] = make_float2(0.f, 0.f);

    fft2048_fwd_reg(z, sRe1, sIm1, sRe2, sIm2, t);

    // pointwise * G (scrambled layout matches alphafft)
    {
        const float4* __restrict__ Gr =
            (const float4*)&g_G[(row & (NFFT - 1)) * LFFT + t * 8];
#pragma unroll
        for (int cc = 0; cc < 4; cc++) {
            float4 g = Gr[cc];
            float2 x0 = z[2 * cc], x1 = z[2 * cc + 1];
            z[2 * cc]     = make_float2(x0.x * g.x - x0.y * g.y, x0.x * g.y + x0.y * g.x);
            z[2 * cc + 1] = make_float2(x1.x * g.z - x1.y * g.w, x1.x * g.w + x1.y * g.z);
        }
    }

    int g  = t >> 2, j2 = t & 3;
    int mA = t >> 5, j1 = t & 31;

    // inverse: shfl-4, conj tw, inv8 -> ex2' (region1)
    inv4sh(z, j2);
    {
        float sw, cw;
        sincospif((float)j2 * (1.0f / 16.0f), &sw, &cw);   // conj
        twiddle_chain(z, make_float2(cw, sw));
        inv8(z);
#pragma unroll
        for (int w = 0; w < 8; w++) {
            int a = g * 36 + j2 + 4 * w;
            sRe1[a] = z[w].x; sIm1[a] = z[w].y;
        }
    }
    __syncthreads();

    // stage B': read bins mB (region1), conj tw, inv8 -> ex1' (region2)
    {
        const int posOf[8] = {0, 2, 4, 6, 1, 3, 5, 7};
#pragma unroll
        for (int mB = 0; mB < 8; mB++) {
            int a = (mA * 8 + mB) * 36 + j1;
            z[posOf[mB]] = make_float2(sRe1[a], sIm1[a]);
        }
        float sw, cw;
        sincospif((float)j1 * (1.0f / 128.0f), &sw, &cw);  // conj
        twiddle_chain(z, make_float2(cw, sw));
        inv8(z);
#pragma unroll
        for (int v = 0; v < 8; v++) {
            int a = mA * 264 + j1 + 32 * v;
            sRe2[a] = z[v].x; sIm2[a] = z[v].y;
        }
    }
    __syncthreads();

    // stage A': read bins mA (region2), conj tw, inv8 -> c[t + 256u], masked |c|^2
    float lsum = 0.f;
    {
        const int posOf[8] = {0, 2, 4, 6, 1, 3, 5, 7};
#pragma unroll
        for (int m = 0; m < 8; m++) {
            int a = m * 264 + t;
            z[posOf[m]] = make_float2(sRe2[a], sIm2[a]);
        }
        float2 w1 = g_stw[T512 + t];
        w1.y = -w1.y;                                      // conj
        twiddle_chain(z, w1);
        inv8(z);
        // valid lags: i <= 513 or i >= 1537;  i = t + 256u
        lsum  = z[0].x * z[0].x + z[0].y * z[0].y;         // u=0: i<=255
        lsum += z[1].x * z[1].x + z[1].y * z[1].y;         // u=1: i<=511
        lsum += z[7].x * z[7].x + z[7].y * z[7].y;         // u=7: i>=1792
        if (t <= 1) lsum += z[2].x * z[2].x + z[2].y * z[2].y;   // i=512,513
        if (t >= 1) lsum += z[6].x * z[6].x + z[6].y * z[6].y;   // i=1537..1791
    }

#pragma unroll
    for (int off = 16; off > 0; off >>= 1)
        lsum += __shfl_down_sync(0xffffffff, lsum, off);
    if ((t & 31) == 0) warpsum[t >> 5] = lsum;
    __syncthreads();
    if (t == 0) {
        float s = 0.f;
#pragma unroll
        for (int w = 0; w < 8; w++) s += warpsum[w];
        atomicAdd(&g_acc, (double)s);
    }
}

__global__ void finalize_kernel(float* out) {
    out[0] = (float)(g_acc / (double)(BATCH * TFRAMES));
}

extern "C" void kernel_launch(void* const* d_in, const int* in_sizes, int n_in,
                              void* d_out, int out_size) {
    const float* wav = (const float*)d_in[0];
    const float* win = (const float*)d_in[1];
    const float* ar  = (const float*)d_in[2];
    const float* ai  = (const float*)d_in[3];

    twinit_kernel<<<4, 256>>>();
    alphafft_kernel<<<7, 256>>>(ar, ai);
    dim3 gG(LFFT / 128, NFFT / GN_PER);
    gcomb_kernel<<<gG, 128>>>();
    dim3 gs(NCHUNK, BATCH);
    stft_kernel<<<gs, 512>>>(wav, win);
    conv_kernel<<<NROWS, 256>>>();
    finalize_kernel<<<1, 1>>>((float*)d_out);
}

// round 11
// speedup vs baseline: 9.2863x; 1.0499x over previous
#include <cuda_runtime.h>

#define NFFT    512
#define HOPSZ   128
#define BATCH   4
#define LSAMP   131072
#define TFRAMES 1025
#define KW      1023
#define NROWS   (BATCH * NFFT)   // 2048
#define LFFT    2048
#define TCH     16
#define NCHUNK  65

// ------------- device scratch (static, no allocs) -------------
__device__ float2 g_Ht[NCHUNK * NROWS * TCH];   // tiled: [chunk][row][16]
__device__ float2 g_B[7 * LFFT];                // scrambled order (t*8+p)
__device__ float2 g_G[NFFT * LFFT];             // scrambled order
__device__ double g_acc;

__device__ __forceinline__ float2 cmul(float2 a, float2 b) {
    return make_float2(a.x * b.x - a.y * b.y, a.x * b.y + a.y * b.x);
}
__device__ __forceinline__ float2 cadd(float2 a, float2 b) { return make_float2(a.x + b.x, a.y + b.y); }
__device__ __forceinline__ float2 csub(float2 a, float2 b) { return make_float2(a.x - b.x, a.y - b.y); }
__device__ __forceinline__ float2 cnegi(float2 a) { return make_float2(a.y, -a.x); }   // -i*a
__device__ __forceinline__ float2 cposi(float2 a) { return make_float2(-a.y, a.x); }   // +i*a

// 8-pt DFT on registers; reg p holds bin binOf[p], binOf={0,4,1,5,2,6,3,7}, posOf={0,2,4,6,1,3,5,7}
__device__ __forceinline__ void fwd8(float2* z) {
    const float r = 0.70710678118654752f;
    const float2 W1 = make_float2(r, -r);
    const float2 W3 = make_float2(-r, -r);
    float2 t0 = cadd(z[0], z[4]), t1 = csub(z[0], z[4]);
    float2 t2 = cadd(z[2], z[6]), u3 = cnegi(csub(z[2], z[6]));
    float2 p0 = cadd(t0, t2), p2 = cadd(t1, u3), p4 = csub(t0, t2), p6 = csub(t1, u3);
    t0 = cadd(z[1], z[5]); t1 = csub(z[1], z[5]);
    t2 = cadd(z[3], z[7]); u3 = cnegi(csub(z[3], z[7]));
    float2 p1 = cadd(t0, t2);
    float2 p3 = cmul(cadd(t1, u3), W1);
    float2 p5 = cnegi(csub(t0, t2));
    float2 p7 = cmul(csub(t1, u3), W3);
    z[0] = cadd(p0, p1); z[1] = csub(p0, p1);
    z[2] = cadd(p2, p3); z[3] = csub(p2, p3);
    z[4] = cadd(p4, p5); z[5] = csub(p4, p5);
    z[6] = cadd(p6, p7); z[7] = csub(p6, p7);
}

// inverse: input in binOf layout, output natural j order (unnormalized x8)
__device__ __forceinline__ void inv8(float2* z) {
    const float r = 0.70710678118654752f;
    const float2 W1c = make_float2(r, r);
    const float2 W3c = make_float2(-r, r);
    float2 q0 = cadd(z[0], z[1]), q1 = csub(z[0], z[1]);
    float2 q2 = cadd(z[2], z[3]), q3 = csub(z[2], z[3]);
    float2 q4 = cadd(z[4], z[5]), q5 = csub(z[4], z[5]);
    float2 q6 = cadd(z[6], z[7]), q7 = csub(z[6], z[7]);
    float2 t0 = cadd(q0, q4), t1 = csub(q0, q4);
    float2 t2 = cadd(q2, q6), v3 = cposi(csub(q2, q6));
    z[0] = cadd(t0, t2); z[2] = cadd(t1, v3); z[4] = csub(t0, t2); z[6] = csub(t1, v3);
    float2 b = cmul(q3, W1c);
    float2 c = cposi(q5);
    float2 d = cmul(q7, W3c);
    t0 = cadd(q1, c); t1 = csub(q1, c);
    t2 = cadd(b, d);  v3 = cposi(csub(b, d));
    z[1] = cadd(t0, t2); z[3] = cadd(t1, v3); z[5] = csub(t0, t2); z[7] = csub(t1, v3);
}

// multiply bin m by w1^m (regs in binOf layout)
__device__ __forceinline__ void twiddle_chain(float2* z, float2 w1) {
    const int posOf[8] = {0, 2, 4, 6, 1, 3, 5, 7};
    float2 wm = w1;
    z[posOf[1]] = cmul(z[posOf[1]], wm);
#pragma unroll
    for (int m = 2; m < 8; m++) {
        wm = cmul(wm, w1);
        z[posOf[m]] = cmul(z[posOf[m]], wm);
    }
}

__device__ __forceinline__ float2 twf(float invden, int j) {
    float s, c;
    sincospif(-(float)j * invden, &s, &c);
    return make_float2(c, s);
}
__device__ __forceinline__ float2 twfc(float invden, int j) {   // conj
    float s, c;
    sincospif((float)j * invden, &s, &c);
    return make_float2(c, s);
}

__device__ __forceinline__ float2 shflx(float2 v, int m) {
    return make_float2(__shfl_xor_sync(0xffffffffu, v.x, m),
                       __shfl_xor_sync(0xffffffffu, v.y, m));
}

// distributed 4-pt DFT across lanes l=j2 (lane&3)
__device__ __forceinline__ void fwd4sh(float2* z, int l) {
#pragma unroll
    for (int p = 0; p < 8; p++) {
        float2 v = z[p];
        float2 q = shflx(v, 2);
        v = (l & 2) ? csub(q, v) : cadd(v, q);
        if (l == 3) v = cnegi(v);
        q = shflx(v, 1);
        v = (l & 1) ? csub(q, v) : cadd(v, q);
        z[p] = v;
    }
}

__device__ __forceinline__ void inv4sh(float2* z, int l) {
#pragma unroll
    for (int p = 0; p < 8; p++) {
        float2 v = z[p];
        float2 q = shflx(v, 1);
        v = (l & 1) ? csub(q, v) : cadd(v, q);
        if (l == 3) v = cposi(v);
        q = shflx(v, 2);
        v = (l & 2) ? csub(q, v) : cadd(v, q);
        z[p] = v;
    }
}

// ---- forward 2048-pt path (8-8-8-4), float2 exchanges, spectrum left in z ----
__device__ __forceinline__ void fft2048_fwd_reg(float2* z, float2* sX1, float2* sX2, int t) {
    const int binOf[8] = {0, 4, 1, 5, 2, 6, 3, 7};
    fwd8(z);
    twiddle_chain(z, twf(1.0f / 1024.0f, t));          // W_2048^t
#pragma unroll
    for (int p = 0; p < 8; p++) sX1[binOf[p] * 256 + t] = z[p];
    __syncthreads();

    int mA = t >> 5, j1 = t & 31;
#pragma unroll
    for (int v = 0; v < 8; v++) z[v] = sX1[mA * 256 + j1 + 32 * v];
    fwd8(z);
    twiddle_chain(z, twf(1.0f / 128.0f, j1));          // W_256^j1
#pragma unroll
    for (int p = 0; p < 8; p++) sX2[(mA * 8 + binOf[p]) * 36 + j1] = z[p];
    __syncthreads();

    int g = t >> 2, j2 = t & 3;
#pragma unroll
    for (int w = 0; w < 8; w++) z[w] = sX2[g * 36 + j2 + 4 * w];
    fwd8(z);
    twiddle_chain(z, twf(1.0f / 16.0f, j2));           // W_32^j2
    fwd4sh(z, j2);
}

// ---------------- alpha rows: conj-FFT + g_acc reset ----------------
__global__ __launch_bounds__(256) void alphafft_kernel(const float* __restrict__ ar,
                                                       const float* __restrict__ ai) {
    __shared__ float2 sX1[2048];
    __shared__ float2 sX2[2304];
    int q = blockIdx.x, t = threadIdx.x;
    if (q == 0 && t == 0) g_acc = 0.0;

    float2 z[8];
#pragma unroll
    for (int u = 0; u < 8; u++) {
        int i = t + 256 * u;
        if (u <= 2 || (u == 3 && t < 255))
            z[u] = make_float2(ar[q * KW + i], -ai[q * KW + i]);
        else
            z[u] = make_float2(0.f, 0.f);
    }
    fft2048_fwd_reg(z, sX1, sX2, t);

    float2* __restrict__ out = &g_B[q * LFFT + t * 8];
#pragma unroll
    for (int p = 0; p < 8; p++)
        out[p] = make_float2(z[p].x, -z[p].y);   // conj
}

// ---------------- G[n,f] ----------------
#define GN_PER 8
__global__ __launch_bounds__(128) void gcomb_kernel() {
    int f  = blockIdx.x * 128 + threadIdx.x;
    int n0 = blockIdx.y * GN_PER;
    float2 Bq[7], p[7], st[7];
#pragma unroll
    for (int q = 0; q < 7; q++) {
        Bq[q] = g_B[q * LFFT + f];
        float qq = (float)(q - 3);
        float s, c;
        sincospif((float)n0 * qq * (1.0f / 256.0f), &s, &c);
        p[q] = make_float2(c, s);
        sincospif(qq * (1.0f / 256.0f), &s, &c);
        st[q] = make_float2(c, s);
    }
    float2* __restrict__ out = &g_G[n0 * LFFT + f];
#pragma unroll
    for (int n = 0; n < GN_PER; n++) {
        float gr = 0.f, gi = 0.f;
#pragma unroll
        for (int q = 0; q < 7; q++) {
            gr += p[q].x * Bq[q].x - p[q].y * Bq[q].y;
            gi += p[q].x * Bq[q].y + p[q].y * Bq[q].x;
        }
        out[(size_t)n * LFFT] = make_float2(gr * (1.0f / (float)LFFT), gi * (1.0f / (float)LFFT));
#pragma unroll
        for (int q = 0; q < 7; q++) p[q] = cmul(p[q], st[q]);
    }
}

// ---------------- STFT: register radix-8, 4 packed FFTs (8 frames) per 256-thread block ----------------
#define WSPAN4 (7 * HOPSZ + NFFT)   // 1408
#define SST    584
__global__ __launch_bounds__(256) void stft_kernel(const float* __restrict__ wav,
                                                   const float* __restrict__ win) {
    __shared__ float sRe[4 * SST];
    __shared__ float sIm[4 * SST];
    __shared__ float sWav[WSPAN4];
    __shared__ float sWin[NFFT];

    int hc  = blockIdx.x;              // half-chunk 0..129 (8 frames each)
    int b   = blockIdx.y;
    int tid = threadIdx.x;             // 256
    int tf0 = hc * 8;
    int f   = tid >> 6;                // packed-FFT index 0..3
    int j   = tid & 63;

    for (int i = tid; i < NFFT; i += 256) sWin[i] = win[i];
    {
        int base = tf0 * HOPSZ - 256;
        const float* __restrict__ wb = wav + b * LSAMP;
#pragma unroll
        for (int k = 0; k < 6; k++) {
            int i = tid + k * 256;
            if (i < WSPAN4) {
                int p = base + i;
                if (p < 0) p = -p;
                if (p >= LSAMP) p = 2 * LSAMP - 2 - p;
                sWav[i] = wb[p];
            }
        }
    }
    __syncthreads();

    float* fRe = &sRe[f * SST];
    float* fIm = &sIm[f * SST];
    float2 z[8];
    const int binOf[8] = {0, 4, 1, 5, 2, 6, 3, 7};

    // stage A: x[j+64u] (frames tf0+2f re, tf0+2f+1 im), DFT-8 + W_512^(j*m)
#pragma unroll
    for (int u = 0; u < 8; u++) {
        int i = j + 64 * u;
        float wv = sWin[i];
        z[u] = make_float2(sWav[256 * f + i] * wv, sWav[256 * f + 128 + i] * wv);
    }
    fwd8(z);
    twiddle_chain(z, twf(1.0f / 256.0f, j));           // W_512^j
#pragma unroll
    for (int p = 0; p < 8; p++) {
        fRe[binOf[p] * 72 + j] = z[p].x;
        fIm[binOf[p] * 72 + j] = z[p].y;
    }
    __syncthreads();

    // stage B
    {
        int m = j >> 3, j0 = j & 7;
#pragma unroll
        for (int u = 0; u < 8; u++) {
            int a = m * 72 + j0 + 8 * u;
            z[u] = make_float2(fRe[a], fIm[a]);
        }
        fwd8(z);
        twiddle_chain(z, twf(1.0f / 32.0f, j0));       // W_64^j0
        __syncthreads();
#pragma unroll
        for (int p = 0; p < 8; p++) {
            int a = (m * 8 + binOf[p]) * 9 + j0;
            fRe[a] = z[p].x;
            fIm[a] = z[p].y;
        }
    }
    __syncthreads();

    // stage C -> natural-order spectrum
    {
#pragma unroll
        for (int u = 0; u < 8; u++) {
            int a = j * 9 + u;
            z[u] = make_float2(fRe[a], fIm[a]);
        }
        fwd8(z);
        __syncthreads();
        int m = j >> 3, mB = j & 7;
#pragma unroll
        for (int p = 0; p < 8; p++) {
            int n = m + 8 * mB + 64 * binOf[p];
            fRe[n] = z[p].x;
            fIm[n] = z[p].y;
        }
    }
    __syncthreads();

    // Hermitian unpack; float4 writes into tiled H
    int chunk = hc >> 1, off8 = (hc & 1) * 8;
#pragma unroll
    for (int k = 0; k < 8; k++) {
        int o = tid + k * 256;             // o = n*4 + p
        int n = o >> 2, p = o & 3;
        int m512 = (NFFT - n) & (NFFT - 1);
        float Znr = sRe[p * SST + n],    Zni = sIm[p * SST + n];
        float Zmr = sRe[p * SST + m512], Zmi = sIm[p * SST + m512];
        int te = tf0 + 2 * p;
        float4 hv;
        if (te <= 1024) {
            hv.x = 0.5f * (Znr + Zmr);  hv.y = 0.5f * (Zni - Zmi);
        } else { hv.x = 0.f; hv.y = 0.f; }
        if (te + 1 <= 1024) {
            hv.z = 0.5f * (Zni + Zmi);  hv.w = -0.5f * (Znr - Zmr);
        } else { hv.z = 0.f; hv.w = 0.f; }
        float4* __restrict__ dst =
            (float4*)&g_Ht[(((size_t)chunk * NROWS + b * NFFT + n) << 4) + off8 + 2 * p];
        *dst = hv;
    }
}

// ---------------- conv: register 8-8-8-4, float2 exchanges, one row per 256-thread block ----------------
__global__ __launch_bounds__(256, 4) void conv_kernel() {
    __shared__ float2 sX1[2048];
    __shared__ float2 sX2[2304];
    __shared__ float warpsum[8];

    int row = blockIdx.x;
    int t   = threadIdx.x;

    float2 z[8];
#pragma unroll
    for (int u = 0; u < 4; u++) {
        int i = t + 256 * u;
        z[u] = g_Ht[(((i >> 4) * NROWS + row) << 4) + (i & 15)];
    }
    z[4] = (t == 0) ? g_Ht[((64 * NROWS + row) << 4)] : make_float2(0.f, 0.f);
    z[5] = make_float2(0.f, 0.f);
    z[6] = make_float2(0.f, 0.f);
    z[7] = make_float2(0.f, 0.f);

    fft2048_fwd_reg(z, sX1, sX2, t);

    // pointwise * G (layouts match alphafft scramble)
    {
        const float4* __restrict__ Gr =
            (const float4*)&g_G[(row & (NFFT - 1)) * LFFT + t * 8];
#pragma unroll
        for (int cc = 0; cc < 4; cc++) {
            float4 g = Gr[cc];
            float2 x0 = z[2 * cc], x1 = z[2 * cc + 1];
            z[2 * cc]     = make_float2(x0.x * g.x - x0.y * g.y, x0.x * g.y + x0.y * g.x);
            z[2 * cc + 1] = make_float2(x1.x * g.z - x1.y * g.w, x1.x * g.w + x1.y * g.z);
        }
    }

    int g  = t >> 2, j2 = t & 3;
    int mA = t >> 5, j1 = t & 31;
    const int posOf[8] = {0, 2, 4, 6, 1, 3, 5, 7};

    // inverse stage C' (per-thread read set == write set, no sync needed before write)
    inv4sh(z, j2);
    twiddle_chain(z, twfc(1.0f / 16.0f, j2));
    inv8(z);
#pragma unroll
    for (int w = 0; w < 8; w++) sX2[g * 36 + j2 + 4 * w] = z[w];
    __syncthreads();

    // inverse stage B'
#pragma unroll
    for (int mB = 0; mB < 8; mB++)
        z[posOf[mB]] = sX2[(mA * 8 + mB) * 36 + j1];
    twiddle_chain(z, twfc(1.0f / 128.0f, j1));
    inv8(z);
#pragma unroll
    for (int v = 0; v < 8; v++) sX1[mA * 256 + j1 + 32 * v] = z[v];
    __syncthreads();

    // inverse stage A' + masked |c|^2
    float lsum = 0.f;
    {
#pragma unroll
        for (int m = 0; m < 8; m++)
            z[posOf[m]] = sX1[m * 256 + t];
        twiddle_chain(z, twfc(1.0f / 1024.0f, t));
        inv8(z);
        lsum  = z[0].x * z[0].x + z[0].y * z[0].y;               // i=t
        lsum += z[1].x * z[1].x + z[1].y * z[1].y;               // i=t+256
        lsum += z[7].x * z[7].x + z[7].y * z[7].y;               // i=t+1792
        if (t <= 1) lsum += z[2].x * z[2].x + z[2].y * z[2].y;   // i=512,513
        if (t >= 1) lsum += z[6].x * z[6].x + z[6].y * z[6].y;   // i=1537..1791
    }

#pragma unroll
    for (int off = 16; off > 0; off >>= 1)
        lsum += __shfl_down_sync(0xffffffff, lsum, off);
    if ((t & 31) == 0) warpsum[t >> 5] = lsum;
    __syncthreads();
    if (t == 0) {
        float s = 0.f;
#pragma unroll
        for (int w = 0; w < 8; w++) s += warpsum[w];
        atomicAdd(&g_acc, (double)s);
    }
}

__global__ void finalize_kernel(float* out) {
    out[0] = (float)(g_acc / (double)(BATCH * TFRAMES));
}

extern "C" void kernel_launch(void* const* d_in, const int* in_sizes, int n_in,
                              void* d_out, int out_size) {
    const float* wav = (const float*)d_in[0];
    const float* win = (const float*)d_in[1];
    const float* ar  = (const float*)d_in[2];
    const float* ai  = (const float*)d_in[3];

    alphafft_kernel<<<7, 256>>>(ar, ai);
    dim3 gG(LFFT / 128, NFFT / GN_PER);
    gcomb_kernel<<<gG, 128>>>();
    dim3 gs(2 * NCHUNK, BATCH);
    stft_kernel<<<gs, 256>>>(wav, win);
    conv_kernel<<<NROWS, 256>>>();
    finalize_kernel<<<1, 1>>>((float*)d_out);
}

// round 12
// speedup vs baseline: 10.2024x; 1.0987x over previous
#include <cuda_runtime.h>

#define NFFT    512
#define HOPSZ   128
#define BATCH   4
#define LSAMP   131072
#define TFRAMES 1025
#define KW      1023
#define NROWS   (BATCH * NFFT)   // 2048
#define LFFT    2048
#define TCH     16
#define NCHUNK  65

// ------------- device scratch (static, no allocs) -------------
__device__ float2 g_Ht[NCHUNK * NROWS * TCH];   // tiled: [chunk][row][16]
__device__ float2 g_B [7 * LFFT];               // conj-input FFT table (scrambled)
__device__ float2 g_B2[7 * LFFT];               // plain-input FFT table (scrambled)
__device__ float2 g_G [NFFT * LFFT];            // spectrum for row n      (scrambled)
__device__ float2 g_G2[NFFT * LFFT];            // spectrum for row 512-n  (scrambled)
__device__ double g_acc;

__device__ __forceinline__ float2 cmul(float2 a, float2 b) {
    return make_float2(a.x * b.x - a.y * b.y, a.x * b.y + a.y * b.x);
}
__device__ __forceinline__ float2 cadd(float2 a, float2 b) { return make_float2(a.x + b.x, a.y + b.y); }
__device__ __forceinline__ float2 csub(float2 a, float2 b) { return make_float2(a.x - b.x, a.y - b.y); }
__device__ __forceinline__ float2 cnegi(float2 a) { return make_float2(a.y, -a.x); }   // -i*a
__device__ __forceinline__ float2 cposi(float2 a) { return make_float2(-a.y, a.x); }   // +i*a

// 8-pt DFT on registers; reg p holds bin binOf[p], binOf={0,4,1,5,2,6,3,7}, posOf={0,2,4,6,1,3,5,7}
__device__ __forceinline__ void fwd8(float2* z) {
    const float r = 0.70710678118654752f;
    const float2 W1 = make_float2(r, -r);
    const float2 W3 = make_float2(-r, -r);
    float2 t0 = cadd(z[0], z[4]), t1 = csub(z[0], z[4]);
    float2 t2 = cadd(z[2], z[6]), u3 = cnegi(csub(z[2], z[6]));
    float2 p0 = cadd(t0, t2), p2 = cadd(t1, u3), p4 = csub(t0, t2), p6 = csub(t1, u3);
    t0 = cadd(z[1], z[5]); t1 = csub(z[1], z[5]);
    t2 = cadd(z[3], z[7]); u3 = cnegi(csub(z[3], z[7]));
    float2 p1 = cadd(t0, t2);
    float2 p3 = cmul(cadd(t1, u3), W1);
    float2 p5 = cnegi(csub(t0, t2));
    float2 p7 = cmul(csub(t1, u3), W3);
    z[0] = cadd(p0, p1); z[1] = csub(p0, p1);
    z[2] = cadd(p2, p3); z[3] = csub(p2, p3);
    z[4] = cadd(p4, p5); z[5] = csub(p4, p5);
    z[6] = cadd(p6, p7); z[7] = csub(p6, p7);
}

// inverse: input in binOf layout, output natural j order (unnormalized x8)
__device__ __forceinline__ void inv8(float2* z) {
    const float r = 0.70710678118654752f;
    const float2 W1c = make_float2(r, r);
    const float2 W3c = make_float2(-r, r);
    float2 q0 = cadd(z[0], z[1]), q1 = csub(z[0], z[1]);
    float2 q2 = cadd(z[2], z[3]), q3 = csub(z[2], z[3]);
    float2 q4 = cadd(z[4], z[5]), q5 = csub(z[4], z[5]);
    float2 q6 = cadd(z[6], z[7]), q7 = csub(z[6], z[7]);
    float2 t0 = cadd(q0, q4), t1 = csub(q0, q4);
    float2 t2 = cadd(q2, q6), v3 = cposi(csub(q2, q6));
    z[0] = cadd(t0, t2); z[2] = cadd(t1, v3); z[4] = csub(t0, t2); z[6] = csub(t1, v3);
    float2 b = cmul(q3, W1c);
    float2 c = cposi(q5);
    float2 d = cmul(q7, W3c);
    t0 = cadd(q1, c); t1 = csub(q1, c);
    t2 = cadd(b, d);  v3 = cposi(csub(b, d));
    z[1] = cadd(t0, t2); z[3] = cadd(t1, v3); z[5] = csub(t0, t2); z[7] = csub(t1, v3);
}

// multiply bin m by w1^m (regs in binOf layout)
__device__ __forceinline__ void twiddle_chain(float2* z, float2 w1) {
    const int posOf[8] = {0, 2, 4, 6, 1, 3, 5, 7};
    float2 wm = w1;
    z[posOf[1]] = cmul(z[posOf[1]], wm);
#pragma unroll
    for (int m = 2; m < 8; m++) {
        wm = cmul(wm, w1);
        z[posOf[m]] = cmul(z[posOf[m]], wm);
    }
}

__device__ __forceinline__ float2 twf(float invden, int j) {
    float s, c;
    sincospif(-(float)j * invden, &s, &c);
    return make_float2(c, s);
}
__device__ __forceinline__ float2 twfc(float invden, int j) {   // conj
    float s, c;
    sincospif((float)j * invden, &s, &c);
    return make_float2(c, s);
}

__device__ __forceinline__ float2 shflx(float2 v, int m) {
    return make_float2(__shfl_xor_sync(0xffffffffu, v.x, m),
                       __shfl_xor_sync(0xffffffffu, v.y, m));
}

// distributed 4-pt DFT across lanes l=j2 (lane&3)
__device__ __forceinline__ void fwd4sh(float2* z, int l) {
#pragma unroll
    for (int p = 0; p < 8; p++) {
        float2 v = z[p];
        float2 q = shflx(v, 2);
        v = (l & 2) ? csub(q, v) : cadd(v, q);
        if (l == 3) v = cnegi(v);
        q = shflx(v, 1);
        v = (l & 1) ? csub(q, v) : cadd(v, q);
        z[p] = v;
    }
}

__device__ __forceinline__ void inv4sh(float2* z, int l) {
#pragma unroll
    for (int p = 0; p < 8; p++) {
        float2 v = z[p];
        float2 q = shflx(v, 1);
        v = (l & 1) ? csub(q, v) : cadd(v, q);
        if (l == 3) v = cposi(v);
        q = shflx(v, 2);
        v = (l & 2) ? csub(q, v) : cadd(v, q);
        z[p] = v;
    }
}

// ---- forward 2048-pt path (8-8-8-4), float2 exchanges, spectrum left in z ----
__device__ __forceinline__ void fft2048_fwd_reg(float2* z, float2* sX1, float2* sX2, int t) {
    const int binOf[8] = {0, 4, 1, 5, 2, 6, 3, 7};
    fwd8(z);
    twiddle_chain(z, twf(1.0f / 1024.0f, t));          // W_2048^t
#pragma unroll
    for (int p = 0; p < 8; p++) sX1[binOf[p] * 256 + t] = z[p];
    __syncthreads();

    int mA = t >> 5, j1 = t & 31;
#pragma unroll
    for (int v = 0; v < 8; v++) z[v] = sX1[mA * 256 + j1 + 32 * v];
    fwd8(z);
    twiddle_chain(z, twf(1.0f / 128.0f, j1));          // W_256^j1
#pragma unroll
    for (int p = 0; p < 8; p++) sX2[(mA * 8 + binOf[p]) * 36 + j1] = z[p];
    __syncthreads();

    int g = t >> 2, j2 = t & 3;
#pragma unroll
    for (int w = 0; w < 8; w++) z[w] = sX2[g * 36 + j2 + 4 * w];
    fwd8(z);
    twiddle_chain(z, twf(1.0f / 16.0f, j2));           // W_32^j2
    fwd4sh(z, j2);
}

// ---- inverse 2048-pt + masked |c|^2 partial sum ----
// Safe to call twice back-to-back: second call's sX2 writes are fenced by the
// first call's barrier between B' (last sX2 reads) and A'.
__device__ __forceinline__ float inv2048_masked(float2* z, float2* sX1, float2* sX2, int t) {
    const int posOf[8] = {0, 2, 4, 6, 1, 3, 5, 7};
    int g  = t >> 2, j2 = t & 3;
    int mA = t >> 5, j1 = t & 31;

    inv4sh(z, j2);
    twiddle_chain(z, twfc(1.0f / 16.0f, j2));
    inv8(z);
#pragma unroll
    for (int w = 0; w < 8; w++) sX2[g * 36 + j2 + 4 * w] = z[w];
    __syncthreads();

#pragma unroll
    for (int mB = 0; mB < 8; mB++)
        z[posOf[mB]] = sX2[(mA * 8 + mB) * 36 + j1];
    twiddle_chain(z, twfc(1.0f / 128.0f, j1));
    inv8(z);
#pragma unroll
    for (int v = 0; v < 8; v++) sX1[mA * 256 + j1 + 32 * v] = z[v];
    __syncthreads();

#pragma unroll
    for (int m = 0; m < 8; m++)
        z[posOf[m]] = sX1[m * 256 + t];
    twiddle_chain(z, twfc(1.0f / 1024.0f, t));
    inv8(z);
    // valid lags i = t + 256u: u=0,1,7 always; u=2 iff t<=1; u=6 iff t>=1
    float lsum;
    lsum  = z[0].x * z[0].x + z[0].y * z[0].y;
    lsum += z[1].x * z[1].x + z[1].y * z[1].y;
    lsum += z[7].x * z[7].x + z[7].y * z[7].y;
    if (t <= 1) lsum += z[2].x * z[2].x + z[2].y * z[2].y;
    if (t >= 1) lsum += z[6].x * z[6].x + z[6].y * z[6].y;
    return lsum;
}

// ---------------- alpha tables: variant 0 -> g_B (conj input), 1 -> g_B2 (plain) ----------------
__global__ __launch_bounds__(256) void alphafft_kernel(const float* __restrict__ ar,
                                                       const float* __restrict__ ai) {
    __shared__ float2 sX1[2048];
    __shared__ float2 sX2[2304];
    int q = blockIdx.x >> 1, var = blockIdx.x & 1, t = threadIdx.x;
    if (blockIdx.x == 0 && t == 0) g_acc = 0.0;

    float sgn = var ? 1.0f : -1.0f;
    float2 z[8];
#pragma unroll
    for (int u = 0; u < 8; u++) {
        int i = t + 256 * u;
        if (u <= 2 || (u == 3 && t < 255))
            z[u] = make_float2(ar[q * KW + i], sgn * ai[q * KW + i]);
        else
            z[u] = make_float2(0.f, 0.f);
    }
    fft2048_fwd_reg(z, sX1, sX2, t);

    float2* __restrict__ out = (var ? g_B2 : g_B) + q * LFFT + t * 8;
#pragma unroll
    for (int p = 0; p < 8; p++)
        out[p] = make_float2(z[p].x, -z[p].y);   // conj
}

// ---------------- G[n,f] and G2[n,f] for n = 0..263 ----------------
#define GN_PER 8
__global__ __launch_bounds__(128) void gcomb_kernel() {
    int f  = blockIdx.x * 128 + threadIdx.x;
    int n0 = blockIdx.y * GN_PER;
    float2 Bq[7], Cq[7], p[7], st[7];
#pragma unroll
    for (int q = 0; q < 7; q++) {
        Bq[q] = g_B [q * LFFT + f];
        Cq[q] = g_B2[q * LFFT + f];
        float qq = (float)(q - 3);
        float s, c;
        sincospif((float)n0 * qq * (1.0f / 256.0f), &s, &c);
        p[q] = make_float2(c, s);
        sincospif(qq * (1.0f / 256.0f), &s, &c);
        st[q] = make_float2(c, s);
    }
    float2* __restrict__ outG  = &g_G [n0 * LFFT + f];
    float2* __restrict__ outG2 = &g_G2[n0 * LFFT + f];
    const float inv = 1.0f / (float)LFFT;
#pragma unroll
    for (int n = 0; n < GN_PER; n++) {
        float gr = 0.f, gi = 0.f, hr = 0.f, hi = 0.f;
#pragma unroll
        for (int q = 0; q < 7; q++) {
            gr += p[q].x * Bq[q].x - p[q].y * Bq[q].y;
            gi += p[q].x * Bq[q].y + p[q].y * Bq[q].x;
            hr += p[q].x * Cq[q].x - p[q].y * Cq[q].y;
            hi += p[q].x * Cq[q].y + p[q].y * Cq[q].x;
        }
        outG [(size_t)n * LFFT] = make_float2(gr * inv, gi * inv);
        outG2[(size_t)n * LFFT] = make_float2(hr * inv, hi * inv);
#pragma unroll
        for (int q = 0; q < 7; q++) p[q] = cmul(p[q], st[q]);
    }
}

// ---------------- STFT: register radix-8, 4 packed FFTs (8 frames) per 256-thread block ----------------
#define WSPAN4 (7 * HOPSZ + NFFT)   // 1408
#define SST    584
__global__ __launch_bounds__(256) void stft_kernel(const float* __restrict__ wav,
                                                   const float* __restrict__ win) {
    __shared__ float sRe[4 * SST];
    __shared__ float sIm[4 * SST];
    __shared__ float sWav[WSPAN4];
    __shared__ float sWin[NFFT];

    int hc  = blockIdx.x;              // half-chunk 0..129
    int b   = blockIdx.y;
    int tid = threadIdx.x;             // 256
    int tf0 = hc * 8;
    int f   = tid >> 6;
    int j   = tid & 63;

    for (int i = tid; i < NFFT; i += 256) sWin[i] = win[i];
    {
        int base = tf0 * HOPSZ - 256;
        const float* __restrict__ wb = wav + b * LSAMP;
#pragma unroll
        for (int k = 0; k < 6; k++) {
            int i = tid + k * 256;
            if (i < WSPAN4) {
                int p = base + i;
                if (p < 0) p = -p;
                if (p >= LSAMP) p = 2 * LSAMP - 2 - p;
                sWav[i] = wb[p];
            }
        }
    }
    __syncthreads();

    float* fRe = &sRe[f * SST];
    float* fIm = &sIm[f * SST];
    float2 z[8];
    const int binOf[8] = {0, 4, 1, 5, 2, 6, 3, 7};

#pragma unroll
    for (int u = 0; u < 8; u++) {
        int i = j + 64 * u;
        float wv = sWin[i];
        z[u] = make_float2(sWav[256 * f + i] * wv, sWav[256 * f + 128 + i] * wv);
    }
    fwd8(z);
    twiddle_chain(z, twf(1.0f / 256.0f, j));           // W_512^j
#pragma unroll
    for (int p = 0; p < 8; p++) {
        fRe[binOf[p] * 72 + j] = z[p].x;
        fIm[binOf[p] * 72 + j] = z[p].y;
    }
    __syncthreads();

    {
        int m = j >> 3, j0 = j & 7;
#pragma unroll
        for (int u = 0; u < 8; u++) {
            int a = m * 72 + j0 + 8 * u;
            z[u] = make_float2(fRe[a], fIm[a]);
        }
        fwd8(z);
        twiddle_chain(z, twf(1.0f / 32.0f, j0));       // W_64^j0
        __syncthreads();
#pragma unroll
        for (int p = 0; p < 8; p++) {
            int a = (m * 8 + binOf[p]) * 9 + j0;
            fRe[a] = z[p].x;
            fIm[a] = z[p].y;
        }
    }
    __syncthreads();

    {
#pragma unroll
        for (int u = 0; u < 8; u++) {
            int a = j * 9 + u;
            z[u] = make_float2(fRe[a], fIm[a]);
        }
        fwd8(z);
        __syncthreads();
        int m = j >> 3, mB = j & 7;
#pragma unroll
        for (int p = 0; p < 8; p++) {
            int n = m + 8 * mB + 64 * binOf[p];
            fRe[n] = z[p].x;
            fIm[n] = z[p].y;
        }
    }
    __syncthreads();

    int chunk = hc >> 1, off8 = (hc & 1) * 8;
#pragma unroll
    for (int k = 0; k < 8; k++) {
        int o = tid + k * 256;             // o = n*4 + p
        int n = o >> 2, p = o & 3;
        int m512 = (NFFT - n) & (NFFT - 1);
        float Znr = sRe[p * SST + n],    Zni = sIm[p * SST + n];
        float Zmr = sRe[p * SST + m512], Zmi = sIm[p * SST + m512];
        int te = tf0 + 2 * p;
        float4 hv;
        if (te <= 1024) {
            hv.x = 0.5f * (Znr + Zmr);  hv.y = 0.5f * (Zni - Zmi);
        } else { hv.x = 0.f; hv.y = 0.f; }
        if (te + 1 <= 1024) {
            hv.z = 0.5f * (Zni + Zmi);  hv.w = -0.5f * (Znr - Zmr);
        } else { hv.z = 0.f; hv.w = 0.f; }
        float4* __restrict__ dst =
            (float4*)&g_Ht[(((size_t)chunk * NROWS + b * NFFT + n) << 4) + off8 + 2 * p];
        *dst = hv;
    }
}

// ---------------- conv: conjugate-pair rows (n, 512-n), one fwd FFT + two inverses ----------------
__global__ __launch_bounds__(256, 4) void conv_kernel() {
    __shared__ float2 sX1[2048];
    __shared__ float2 sX2[2304];
    __shared__ float2 sX3[2048];
    __shared__ float warpsum[8];

    int n   = blockIdx.x;              // 0..256
    int b   = blockIdx.y;
    int row = b * NFFT + n;
    int t   = threadIdx.x;
    bool dual = (n != 0) && (n != 256);

    float2 z[8];
#pragma unroll
    for (int u = 0; u < 4; u++) {
        int i = t + 256 * u;
        z[u] = g_Ht[(((i >> 4) * NROWS + row) << 4) + (i & 15)];
    }
    z[4] = (t == 0) ? g_Ht[((64 * NROWS + row) << 4)] : make_float2(0.f, 0.f);
    z[5] = make_float2(0.f, 0.f);
    z[6] = make_float2(0.f, 0.f);
    z[7] = make_float2(0.f, 0.f);

    fft2048_fwd_reg(z, sX1, sX2, t);

    // stash y2 = spectrum * G2 into sX3 (same-thread write/read, no sync needed)
    if (dual) {
        const float4* __restrict__ G2r = (const float4*)&g_G2[(size_t)n * LFFT + t * 8];
#pragma unroll
        for (int cc = 0; cc < 4; cc++) {
            float4 g = G2r[cc];
            float2 x0 = z[2 * cc], x1 = z[2 * cc + 1];
            sX3[(2 * cc)     * 256 + t] = make_float2(x0.x * g.x - x0.y * g.y, x0.x * g.y + x0.y * g.x);
            sX3[(2 * cc + 1) * 256 + t] = make_float2(x1.x * g.z - x1.y * g.w, x1.x * g.w + x1.y * g.z);
        }
    }

    // y1 = spectrum * G
    {
        const float4* __restrict__ Gr = (const float4*)&g_G[(size_t)n * LFFT + t * 8];
#pragma unroll
        for (int cc = 0; cc < 4; cc++) {
            float4 g = Gr[cc];
            float2 x0 = z[2 * cc], x1 = z[2 * cc + 1];
            z[2 * cc]     = make_float2(x0.x * g.x - x0.y * g.y, x0.x * g.y + x0.y * g.x);
            z[2 * cc + 1] = make_float2(x1.x * g.z - x1.y * g.w, x1.x * g.w + x1.y * g.z);
        }
    }

    float lsum = inv2048_masked(z, sX1, sX2, t);

    if (dual) {
#pragma unroll
        for (int p = 0; p < 8; p++) z[p] = sX3[p * 256 + t];
        lsum += inv2048_masked(z, sX1, sX2, t);
    }

#pragma unroll
    for (int off = 16; off > 0; off >>= 1)
        lsum += __shfl_down_sync(0xffffffff, lsum, off);
    if ((t & 31) == 0) warpsum[t >> 5] = lsum;
    __syncthreads();
    if (t == 0) {
        float s = 0.f;
#pragma unroll
        for (int w = 0; w < 8; w++) s += warpsum[w];
        atomicAdd(&g_acc, (double)s);
    }
}

__global__ void finalize_kernel(float* out) {
    out[0] = (float)(g_acc / (double)(BATCH * TFRAMES));
}

extern "C" void kernel_launch(void* const* d_in, const int* in_sizes, int n_in,
                              void* d_out, int out_size) {
    const float* wav = (const float*)d_in[0];
    const float* win = (const float*)d_in[1];
    const float* ar  = (const float*)d_in[2];
    const float* ai  = (const float*)d_in[3];

    alphafft_kernel<<<14, 256>>>(ar, ai);
    dim3 gG(LFFT / 128, 33);                 // n = 0..263 (covers 0..256 needed)
    gcomb_kernel<<<gG, 128>>>();
    dim3 gs(2 * NCHUNK, BATCH);
    stft_kernel<<<gs, 256>>>(wav, win);
    dim3 gc(257, BATCH);
    conv_kernel<<<gc, 256>>>();
    finalize_kernel<<<1, 1>>>((float*)d_out);
}

// round 14
// speedup vs baseline: 10.3685x; 1.0163x over previous
#include <cuda_runtime.h>

#define NFFT    512
#define HOPSZ   128
#define BATCH   4
#define LSAMP   131072
#define TFRAMES 1025
#define KW      1023
#define NROWS   (BATCH * NFFT)   // 2048
#define LFFT    2048
#define TCH     16
#define NCHUNK  65

// ------------- device scratch (static, no allocs) -------------
__device__ float2 g_Ht[NCHUNK * NROWS * TCH];   // tiled: [chunk][row][16]
__device__ float2 g_B [7 * LFFT];               // conj-input FFT table (scrambled)
__device__ float2 g_B2[7 * LFFT];               // plain-input FFT table (scrambled)
__device__ float2 g_G [NFFT * LFFT];            // spectrum for row n      (scrambled)
__device__ float2 g_G2[NFFT * LFFT];            // spectrum for row 512-n  (scrambled)
__device__ double g_acc;
__device__ unsigned g_ticket;                   // zero-init; reset by last conv block

__device__ __forceinline__ float2 cmul(float2 a, float2 b) {
    return make_float2(a.x * b.x - a.y * b.y, a.x * b.y + a.y * b.x);
}
__device__ __forceinline__ float2 cadd(float2 a, float2 b) { return make_float2(a.x + b.x, a.y + b.y); }
__device__ __forceinline__ float2 csub(float2 a, float2 b) { return make_float2(a.x - b.x, a.y - b.y); }
__device__ __forceinline__ float2 cnegi(float2 a) { return make_float2(a.y, -a.x); }   // -i*a
__device__ __forceinline__ float2 cposi(float2 a) { return make_float2(-a.y, a.x); }   // +i*a

// 8-pt DFT on registers; reg p holds bin binOf[p], binOf={0,4,1,5,2,6,3,7}, posOf={0,2,4,6,1,3,5,7}
__device__ __forceinline__ void fwd8(float2* z) {
    const float r = 0.70710678118654752f;
    const float2 W1 = make_float2(r, -r);
    const float2 W3 = make_float2(-r, -r);
    float2 t0 = cadd(z[0], z[4]), t1 = csub(z[0], z[4]);
    float2 t2 = cadd(z[2], z[6]), u3 = cnegi(csub(z[2], z[6]));
    float2 p0 = cadd(t0, t2), p2 = cadd(t1, u3), p4 = csub(t0, t2), p6 = csub(t1, u3);
    t0 = cadd(z[1], z[5]); t1 = csub(z[1], z[5]);
    t2 = cadd(z[3], z[7]); u3 = cnegi(csub(z[3], z[7]));
    float2 p1 = cadd(t0, t2);
    float2 p3 = cmul(cadd(t1, u3), W1);
    float2 p5 = cnegi(csub(t0, t2));
    float2 p7 = cmul(csub(t1, u3), W3);
    z[0] = cadd(p0, p1); z[1] = csub(p0, p1);
    z[2] = cadd(p2, p3); z[3] = csub(p2, p3);
    z[4] = cadd(p4, p5); z[5] = csub(p4, p5);
    z[6] = cadd(p6, p7); z[7] = csub(p6, p7);
}

// inverse: input in binOf layout, output natural j order (unnormalized x8)
__device__ __forceinline__ void inv8(float2* z) {
    const float r = 0.70710678118654752f;
    const float2 W1c = make_float2(r, r);
    const float2 W3c = make_float2(-r, r);
    float2 q0 = cadd(z[0], z[1]), q1 = csub(z[0], z[1]);
    float2 q2 = cadd(z[2], z[3]), q3 = csub(z[2], z[3]);
    float2 q4 = cadd(z[4], z[5]), q5 = csub(z[4], z[5]);
    float2 q6 = cadd(z[6], z[7]), q7 = csub(z[6], z[7]);
    float2 t0 = cadd(q0, q4), t1 = csub(q0, q4);
    float2 t2 = cadd(q2, q6), v3 = cposi(csub(q2, q6));
    z[0] = cadd(t0, t2); z[2] = cadd(t1, v3); z[4] = csub(t0, t2); z[6] = csub(t1, v3);
    float2 b = cmul(q3, W1c);
    float2 c = cposi(q5);
    float2 d = cmul(q7, W3c);
    t0 = cadd(q1, c); t1 = csub(q1, c);
    t2 = cadd(b, d);  v3 = cposi(csub(b, d));
    z[1] = cadd(t0, t2); z[3] = cadd(t1, v3); z[5] = csub(t0, t2); z[7] = csub(t1, v3);
}

// multiply bin m by w1^m (regs in binOf layout); power tree for ILP
__device__ __forceinline__ void twiddle_chain(float2* z, float2 w1) {
    const int posOf[8] = {0, 2, 4, 6, 1, 3, 5, 7};
    float2 w2 = cmul(w1, w1);
    float2 w3 = cmul(w2, w1);
    float2 w4 = cmul(w2, w2);
    float2 w5 = cmul(w3, w2);
    float2 w6 = cmul(w3, w3);
    float2 w7 = cmul(w4, w3);
    z[posOf[1]] = cmul(z[posOf[1]], w1);
    z[posOf[2]] = cmul(z[posOf[2]], w2);
    z[posOf[3]] = cmul(z[posOf[3]], w3);
    z[posOf[4]] = cmul(z[posOf[4]], w4);
    z[posOf[5]] = cmul(z[posOf[5]], w5);
    z[posOf[6]] = cmul(z[posOf[6]], w6);
    z[posOf[7]] = cmul(z[posOf[7]], w7);
}

__device__ __forceinline__ float2 twf(float invden, int j) {
    float s, c;
    sincospif(-(float)j * invden, &s, &c);
    return make_float2(c, s);
}
__device__ __forceinline__ float2 twfc(float invden, int j) {   // conj
    float s, c;
    sincospif((float)j * invden, &s, &c);
    return make_float2(c, s);
}

__device__ __forceinline__ float2 shflx(float2 v, int m) {
    return make_float2(__shfl_xor_sync(0xffffffffu, v.x, m),
                       __shfl_xor_sync(0xffffffffu, v.y, m));
}

// distributed 4-pt DFT across lanes l=j2 (lane&3)
__device__ __forceinline__ void fwd4sh(float2* z, int l) {
#pragma unroll
    for (int p = 0; p < 8; p++) {
        float2 v = z[p];
        float2 q = shflx(v, 2);
        v = (l & 2) ? csub(q, v) : cadd(v, q);
        if (l == 3) v = cnegi(v);
        q = shflx(v, 1);
        v = (l & 1) ? csub(q, v) : cadd(v, q);
        z[p] = v;
    }
}

__device__ __forceinline__ void inv4sh(float2* z, int l) {
#pragma unroll
    for (int p = 0; p < 8; p++) {
        float2 v = z[p];
        float2 q = shflx(v, 1);
        v = (l & 1) ? csub(q, v) : cadd(v, q);
        if (l == 3) v = cposi(v);
        q = shflx(v, 2);
        v = (l & 2) ? csub(q, v) : cadd(v, q);
        z[p] = v;
    }
}

// ---- forward 2048-pt path (8-8-8-4), float2 exchanges, spectrum left in z ----
__device__ __forceinline__ void fft2048_fwd_reg(float2* z, float2* sX1, float2* sX2, int t) {
    const int binOf[8] = {0, 4, 1, 5, 2, 6, 3, 7};
    fwd8(z);
    twiddle_chain(z, twf(1.0f / 1024.0f, t));          // W_2048^t
#pragma unroll
    for (int p = 0; p < 8; p++) sX1[binOf[p] * 256 + t] = z[p];
    __syncthreads();

    int mA = t >> 5, j1 = t & 31;
#pragma unroll
    for (int v = 0; v < 8; v++) z[v] = sX1[mA * 256 + j1 + 32 * v];
    fwd8(z);
    twiddle_chain(z, twf(1.0f / 128.0f, j1));          // W_256^j1
#pragma unroll
    for (int p = 0; p < 8; p++) sX2[(mA * 8 + binOf[p]) * 36 + j1] = z[p];
    __syncthreads();

    int g = t >> 2, j2 = t & 3;
#pragma unroll
    for (int w = 0; w < 8; w++) z[w] = sX2[g * 36 + j2 + 4 * w];
    fwd8(z);
    twiddle_chain(z, twf(1.0f / 16.0f, j2));           // W_32^j2
    fwd4sh(z, j2);
}

// ---- inverse 2048-pt + masked |c|^2 partial sum (direct masked last stage) ----
// Safe to call twice back-to-back: second call's sX2 writes are fenced by the
// first call's barrier between B' (last sX2 reads) and the final stage.
__device__ __forceinline__ float inv2048_masked(float2* z, float2* sX1, float2* sX2, int t) {
    const int posOf[8] = {0, 2, 4, 6, 1, 3, 5, 7};
    int g  = t >> 2, j2 = t & 3;
    int mA = t >> 5, j1 = t & 31;

    inv4sh(z, j2);
    twiddle_chain(z, twfc(1.0f / 16.0f, j2));
    inv8(z);
#pragma unroll
    for (int w = 0; w < 8; w++) sX2[g * 36 + j2 + 4 * w] = z[w];
    __syncthreads();

#pragma unroll
    for (int mB = 0; mB < 8; mB++)
        z[posOf[mB]] = sX2[(mA * 8 + mB) * 36 + j1];
    twiddle_chain(z, twfc(1.0f / 128.0f, j1));
    inv8(z);
#pragma unroll
    for (int v = 0; v < 8; v++) sX1[mA * 256 + j1 + 32 * v] = z[v];
    __syncthreads();

    // final stage: only outputs u=0,1,7 (+2 for t<=1, +6 for t>=1)
    float2 y0, y1, y2v, y3, y4, y5, y6v, y7;
    {
        float2 w1 = twfc(1.0f / 1024.0f, t);
        float2 w2 = cmul(w1, w1);
        float2 w3 = cmul(w2, w1);
        float2 w4 = cmul(w2, w2);
        float2 w5 = cmul(w3, w2);
        float2 w6 = cmul(w3, w3);
        float2 w7 = cmul(w4, w3);
        y0  = sX1[t];
        y1  = cmul(sX1[256 + t],  w1);
        y2v = cmul(sX1[512 + t],  w2);
        y3  = cmul(sX1[768 + t],  w3);
        y4  = cmul(sX1[1024 + t], w4);
        y5  = cmul(sX1[1280 + t], w5);
        y6v = cmul(sX1[1536 + t], w6);
        y7  = cmul(sX1[1792 + t], w7);
    }
    const float r = 0.70710678118654752f;
    float2 P04 = cadd(y0, y4),  M04 = csub(y0, y4);
    float2 P26 = cadd(y2v, y6v), M26 = csub(y2v, y6v);
    float2 T1  = cadd(y1, y5),  S1  = csub(y1, y5);
    float2 T3  = cadd(y3, y7),  S3  = csub(y3, y7);
    float2 x0 = cadd(cadd(P04, P26), cadd(T1, T3));                    // c[t]... wait: x0 = sum = output u=0? yes
    float2 sm = csub(S1, S3), sp = cadd(S1, S3);
    float2 a = make_float2(M04.x + r * sm.x, M04.y + r * sm.y);        // (x1+x7)/2
    float2 b = make_float2(M26.x + r * sp.x, M26.y + r * sp.y);        // (x1-x7)/(2i)
    float lsum = x0.x * x0.x + x0.y * x0.y
               + 2.0f * (a.x * a.x + a.y * a.y + b.x * b.x + b.y * b.y);
    float2 e = csub(P04, P26);                                         // (x2+x6)/2
    float2 f = csub(T1, T3);                                           // (x2-x6)/(2i)
    if (t == 0) {
        float2 x2 = make_float2(e.x - f.y, e.y + f.x);
        lsum += x2.x * x2.x + x2.y * x2.y;
    } else if (t == 1) {
        lsum += 2.0f * (e.x * e.x + e.y * e.y + f.x * f.x + f.y * f.y);
    } else {
        float2 x6 = make_float2(e.x + f.y, e.y - f.x);
        lsum += x6.x * x6.x + x6.y * x6.y;
    }
    return lsum;
}

// ---------------- alpha tables: variant 0 -> g_B (conj input), 1 -> g_B2 (plain) ----------------
__global__ __launch_bounds__(256) void alphafft_kernel(const float* __restrict__ ar,
                                                       const float* __restrict__ ai) {
    __shared__ float2 sX1[2048];
    __shared__ float2 sX2[2304];
    int q = blockIdx.x >> 1, var = blockIdx.x & 1, t = threadIdx.x;
    if (blockIdx.x == 0 && t == 0) g_acc = 0.0;

    float sgn = var ? 1.0f : -1.0f;
    float2 z[8];
#pragma unroll
    for (int u = 0; u < 8; u++) {
        int i = t + 256 * u;
        if (u <= 2 || (u == 3 && t < 255))
            z[u] = make_float2(ar[q * KW + i], sgn * ai[q * KW + i]);
        else
            z[u] = make_float2(0.f, 0.f);
    }
    fft2048_fwd_reg(z, sX1, sX2, t);

    float2* __restrict__ out = (var ? g_B2 : g_B) + q * LFFT + t * 8;
#pragma unroll
    for (int p = 0; p < 8; p++)
        out[p] = make_float2(z[p].x, -z[p].y);   // conj
}

// ---------------- G[n,f] and G2[n,f] for n = 0..263 ----------------
#define GN_PER 8
__global__ __launch_bounds__(128) void gcomb_kernel() {
    int f  = blockIdx.x * 128 + threadIdx.x;
    int n0 = blockIdx.y * GN_PER;
    float2 Bq[7], Cq[7], p[7], st[7];
#pragma unroll
    for (int q = 0; q < 7; q++) {
        Bq[q] = g_B [q * LFFT + f];
        Cq[q] = g_B2[q * LFFT + f];
        float qq = (float)(q - 3);
        float s, c;
        sincospif((float)n0 * qq * (1.0f / 256.0f), &s, &c);
        p[q] = make_float2(c, s);
        sincospif(qq * (1.0f / 256.0f), &s, &c);
        st[q] = make_float2(c, s);
    }
    float2* __restrict__ outG  = &g_G [n0 * LFFT + f];
    float2* __restrict__ outG2 = &g_G2[n0 * LFFT + f];
    const float inv = 1.0f / (float)LFFT;
#pragma unroll
    for (int n = 0; n < GN_PER; n++) {
        float gr = 0.f, gi = 0.f, hr = 0.f, hi = 0.f;
#pragma unroll
        for (int q = 0; q < 7; q++) {
            gr += p[q].x * Bq[q].x - p[q].y * Bq[q].y;
            gi += p[q].x * Bq[q].y + p[q].y * Bq[q].x;
            hr += p[q].x * Cq[q].x - p[q].y * Cq[q].y;
            hi += p[q].x * Cq[q].y + p[q].y * Cq[q].x;
        }
        outG [(size_t)n * LFFT] = make_float2(gr * inv, gi * inv);
        outG2[(size_t)n * LFFT] = make_float2(hr * inv, hi * inv);
#pragma unroll
        for (int q = 0; q < 7; q++) p[q] = cmul(p[q], st[q]);
    }
}

// ---------------- STFT: register radix-8, 4 packed FFTs (8 frames) per 256-thread block ----------------
#define WSPAN4 (7 * HOPSZ + NFFT)   // 1408
#define SST    584
__global__ __launch_bounds__(256) void stft_kernel(const float* __restrict__ wav,
                                                   const float* __restrict__ win) {
    __shared__ float sRe[4 * SST];
    __shared__ float sIm[4 * SST];
    __shared__ float sWav[WSPAN4];
    __shared__ float sWin[NFFT];

    int hc  = blockIdx.x;              // half-chunk 0..129
    int b   = blockIdx.y;
    int tid = threadIdx.x;             // 256
    int tf0 = hc * 8;
    int f   = tid >> 6;
    int j   = tid & 63;

    for (int i = tid; i < NFFT; i += 256) sWin[i] = win[i];
    {
        int base = tf0 * HOPSZ - 256;
        const float* __restrict__ wb = wav + b * LSAMP;
#pragma unroll
        for (int k = 0; k < 6; k++) {
            int i = tid + k * 256;
            if (i < WSPAN4) {
                int p = base + i;
                if (p < 0) p = -p;
                if (p >= LSAMP) p = 2 * LSAMP - 2 - p;
                sWav[i] = wb[p];
            }
        }
    }
    __syncthreads();

    float* fRe = &sRe[f * SST];
    float* fIm = &sIm[f * SST];
    float2 z[8];
    const int binOf[8] = {0, 4, 1, 5, 2, 6, 3, 7};

#pragma unroll
    for (int u = 0; u < 8; u++) {
        int i = j + 64 * u;
        float wv = sWin[i];
        z[u] = make_float2(sWav[256 * f + i] * wv, sWav[256 * f + 128 + i] * wv);
    }
    fwd8(z);
    twiddle_chain(z, twf(1.0f / 256.0f, j));           // W_512^j
#pragma unroll
    for (int p = 0; p < 8; p++) {
        fRe[binOf[p] * 72 + j] = z[p].x;
        fIm[binOf[p] * 72 + j] = z[p].y;
    }
    __syncthreads();

    {
        int m = j >> 3, j0 = j & 7;
#pragma unroll
        for (int u = 0; u < 8; u++) {
            int a = m * 72 + j0 + 8 * u;
            z[u] = make_float2(fRe[a], fIm[a]);
        }
        fwd8(z);
        twiddle_chain(z, twf(1.0f / 32.0f, j0));       // W_64^j0
        __syncthreads();
#pragma unroll
        for (int p = 0; p < 8; p++) {
            int a = (m * 8 + binOf[p]) * 9 + j0;
            fRe[a] = z[p].x;
            fIm[a] = z[p].y;
        }
    }
    __syncthreads();

    {
#pragma unroll
        for (int u = 0; u < 8; u++) {
            int a = j * 9 + u;
            z[u] = make_float2(fRe[a], fIm[a]);
        }
        fwd8(z);
        __syncthreads();
        int m = j >> 3, mB = j & 7;
#pragma unroll
        for (int p = 0; p < 8; p++) {
            int n = m + 8 * mB + 64 * binOf[p];
            fRe[n] = z[p].x;
            fIm[n] = z[p].y;
        }
    }
    __syncthreads();

    int chunk = hc >> 1, off8 = (hc & 1) * 8;
#pragma unroll
    for (int k = 0; k < 8; k++) {
        int o = tid + k * 256;             // o = n*4 + p
        int n = o >> 2, p = o & 3;
        int m512 = (NFFT - n) & (NFFT - 1);
        float Znr = sRe[p * SST + n],    Zni = sIm[p * SST + n];
        float Zmr = sRe[p * SST + m512], Zmi = sIm[p * SST + m512];
        int te = tf0 + 2 * p;
        float4 hv;
        if (te <= 1024) {
            hv.x = 0.5f * (Znr + Zmr);  hv.y = 0.5f * (Zni - Zmi);
        } else { hv.x = 0.f; hv.y = 0.f; }
        if (te + 1 <= 1024) {
            hv.z = 0.5f * (Zni + Zmi);  hv.w = -0.5f * (Znr - Zmr);
        } else { hv.z = 0.f; hv.w = 0.f; }
        float4* __restrict__ dst =
            (float4*)&g_Ht[(((size_t)chunk * NROWS + b * NFFT + n) << 4) + off8 + 2 * p];
        *dst = hv;
    }
}

// ---------------- conv: conjugate-pair rows, fused finalize ----------------
#define CONV_BLOCKS (257 * BATCH)
__global__ __launch_bounds__(256, 4) void conv_kernel(float* __restrict__ out) {
    __shared__ float2 sX1[2048];
    __shared__ float2 sX2[2304];
    __shared__ float4 sX3[1024];
    __shared__ float warpsum[8];

    int n   = blockIdx.x;              // 0..256
    int b   = blockIdx.y;
    int row = b * NFFT + n;
    int t   = threadIdx.x;
    bool dual = (n != 0) && (n != 256);

    float2 z[8];
#pragma unroll
    for (int u = 0; u < 4; u++) {
        int i = t + 256 * u;
        z[u] = g_Ht[(((i >> 4) * NROWS + row) << 4) + (i & 15)];
    }
    z[4] = (t == 0) ? g_Ht[((64 * NROWS + row) << 4)] : make_float2(0.f, 0.f);
    z[5] = make_float2(0.f, 0.f);
    z[6] = make_float2(0.f, 0.f);
    z[7] = make_float2(0.f, 0.f);

    fft2048_fwd_reg(z, sX1, sX2, t);

    // stash y2 = spectrum * G2 into sX3 (same-thread write/read, float4-packed)
    if (dual) {
        const float4* __restrict__ G2r = (const float4*)&g_G2[(size_t)n * LFFT + t * 8];
#pragma unroll
        for (int cc = 0; cc < 4; cc++) {
            float4 g = G2r[cc];
            float2 x0 = z[2 * cc], x1 = z[2 * cc + 1];
            float4 s;
            s.x = x0.x * g.x - x0.y * g.y;  s.y = x0.x * g.y + x0.y * g.x;
            s.z = x1.x * g.z - x1.y * g.w;  s.w = x1.x * g.w + x1.y * g.z;
            sX3[cc * 256 + t] = s;
        }
    }

    // y1 = spectrum * G
    {
        const float4* __restrict__ Gr = (const float4*)&g_G[(size_t)n * LFFT + t * 8];
#pragma unroll
        for (int cc = 0; cc < 4; cc++) {
            float4 g = Gr[cc];
            float2 x0 = z[2 * cc], x1 = z[2 * cc + 1];
            z[2 * cc]     = make_float2(x0.x * g.x - x0.y * g.y, x0.x * g.y + x0.y * g.x);
            z[2 * cc + 1] = make_float2(x1.x * g.z - x1.y * g.w, x1.x * g.w + x1.y * g.z);
        }
    }

    float lsum = inv2048_masked(z, sX1, sX2, t);

    if (dual) {
#pragma unroll
        for (int cc = 0; cc < 4; cc++) {
            float4 s = sX3[cc * 256 + t];
            z[2 * cc]     = make_float2(s.x, s.y);
            z[2 * cc + 1] = make_float2(s.z, s.w);
        }
        lsum += inv2048_masked(z, sX1, sX2, t);
    }

#pragma unroll
    for (int off = 16; off > 0; off >>= 1)
        lsum += __shfl_down_sync(0xffffffff, lsum, off);
    if ((t & 31) == 0) warpsum[t >> 5] = lsum;
    __syncthreads();
    if (t == 0) {
        float s = 0.f;
#pragma unroll
        for (int w = 0; w < 8; w++) s += warpsum[w];
        atomicAdd(&g_acc, (double)s);
        __threadfence();
        unsigned old = atomicAdd(&g_ticket, 1u);
        if (old == (unsigned)(CONV_BLOCKS - 1)) {
            double v = atomicAdd(&g_acc, 0.0);
            out[0] = (float)(v / (double)(BATCH * TFRAMES));
            g_ticket = 0;                 // reset for next graph replay
        }
    }
}

extern "C" void kernel_launch(void* const* d_in, const int* in_sizes, int n_in,
                              void* d_out, int out_size) {
    const float* wav = (const float*)d_in[0];
    const float* win = (const float*)d_in[1];
    const float* ar  = (const float*)d_in[2];
    const float* ai  = (const float*)d_in[3];

    alphafft_kernel<<<14, 256>>>(ar, ai);
    dim3 gG(LFFT / 128, 33);                 // n = 0..263 (covers 0..256 needed)
    gcomb_kernel<<<gG, 128>>>();
    dim3 gs(2 * NCHUNK, BATCH);
    stft_kernel<<<gs, 256>>>(wav, win);
    dim3 gc(257, BATCH);
    conv_kernel<<<gc, 256>>>((float*)d_out);
}

// round 16
// speedup vs baseline: 10.4221x; 1.0052x over previous
#include <cuda_runtime.h>

#define NFFT    512
#define HOPSZ   128
#define BATCH   4
#define LSAMP   131072
#define TFRAMES 1025
#define KW      1023
#define NROWS   (BATCH * NFFT)   // 2048
#define LFFT    2048
#define TCH     16
#define NCHUNK  65

// ------------- device scratch (static, no allocs) -------------
__device__ float2 g_Ht[NCHUNK * NROWS * TCH];   // tiled: [chunk][row][16]
__device__ float2 g_B [7 * LFFT];               // conj-input FFT table (scrambled)
__device__ float2 g_B2[7 * LFFT];               // plain-input FFT table (scrambled)
__device__ float2 g_G [NFFT * LFFT];            // spectrum for row n      (scrambled)
__device__ float2 g_G2[NFFT * LFFT];            // spectrum for row 512-n  (scrambled)
__device__ double g_acc;
__device__ unsigned g_ticket;                   // zero-init; reset by last conv block

__device__ __forceinline__ float2 cmul(float2 a, float2 b) {
    return make_float2(a.x * b.x - a.y * b.y, a.x * b.y + a.y * b.x);
}
__device__ __forceinline__ float2 cadd(float2 a, float2 b) { return make_float2(a.x + b.x, a.y + b.y); }
__device__ __forceinline__ float2 csub(float2 a, float2 b) { return make_float2(a.x - b.x, a.y - b.y); }
__device__ __forceinline__ float2 cnegi(float2 a) { return make_float2(a.y, -a.x); }   // -i*a
__device__ __forceinline__ float2 cposi(float2 a) { return make_float2(-a.y, a.x); }   // +i*a

// 8-pt DFT on registers; reg p holds bin binOf[p], binOf={0,4,1,5,2,6,3,7}, posOf={0,2,4,6,1,3,5,7}
__device__ __forceinline__ void fwd8(float2* z) {
    const float r = 0.70710678118654752f;
    const float2 W1 = make_float2(r, -r);
    const float2 W3 = make_float2(-r, -r);
    float2 t0 = cadd(z[0], z[4]), t1 = csub(z[0], z[4]);
    float2 t2 = cadd(z[2], z[6]), u3 = cnegi(csub(z[2], z[6]));
    float2 p0 = cadd(t0, t2), p2 = cadd(t1, u3), p4 = csub(t0, t2), p6 = csub(t1, u3);
    t0 = cadd(z[1], z[5]); t1 = csub(z[1], z[5]);
    t2 = cadd(z[3], z[7]); u3 = cnegi(csub(z[3], z[7]));
    float2 p1 = cadd(t0, t2);
    float2 p3 = cmul(cadd(t1, u3), W1);
    float2 p5 = cnegi(csub(t0, t2));
    float2 p7 = cmul(csub(t1, u3), W3);
    z[0] = cadd(p0, p1); z[1] = csub(p0, p1);
    z[2] = cadd(p2, p3); z[3] = csub(p2, p3);
    z[4] = cadd(p4, p5); z[5] = csub(p4, p5);
    z[6] = cadd(p6, p7); z[7] = csub(p6, p7);
}

// inverse: input in binOf layout, output natural j order (unnormalized x8)
__device__ __forceinline__ void inv8(float2* z) {
    const float r = 0.70710678118654752f;
    const float2 W1c = make_float2(r, r);
    const float2 W3c = make_float2(-r, r);
    float2 q0 = cadd(z[0], z[1]), q1 = csub(z[0], z[1]);
    float2 q2 = cadd(z[2], z[3]), q3 = csub(z[2], z[3]);
    float2 q4 = cadd(z[4], z[5]), q5 = csub(z[4], z[5]);
    float2 q6 = cadd(z[6], z[7]), q7 = csub(z[6], z[7]);
    float2 t0 = cadd(q0, q4), t1 = csub(q0, q4);
    float2 t2 = cadd(q2, q6), v3 = cposi(csub(q2, q6));
    z[0] = cadd(t0, t2); z[2] = cadd(t1, v3); z[4] = csub(t0, t2); z[6] = csub(t1, v3);
    float2 b = cmul(q3, W1c);
    float2 c = cposi(q5);
    float2 d = cmul(q7, W3c);
    t0 = cadd(q1, c); t1 = csub(q1, c);
    t2 = cadd(b, d);  v3 = cposi(csub(b, d));
    z[1] = cadd(t0, t2); z[3] = cadd(t1, v3); z[5] = csub(t0, t2); z[7] = csub(t1, v3);
}

// build w[i] = w1^(i+1), i=0..6, via power tree
__device__ __forceinline__ void make_tw7(float2 w1, float2* w) {
    w[0] = w1;
    w[1] = cmul(w1, w1);
    w[2] = cmul(w[1], w1);
    w[3] = cmul(w[1], w[1]);
    w[4] = cmul(w[2], w[1]);
    w[5] = cmul(w[2], w[2]);
    w[6] = cmul(w[3], w[2]);
}

// apply precomputed powers to regs in binOf layout
__device__ __forceinline__ void twiddle_apply(float2* z, const float2* w) {
    const int posOf[8] = {0, 2, 4, 6, 1, 3, 5, 7};
#pragma unroll
    for (int m = 1; m < 8; m++)
        z[posOf[m]] = cmul(z[posOf[m]], w[m - 1]);
}

// multiply bin m by w1^m (regs in binOf layout); tree internally
__device__ __forceinline__ void twiddle_chain(float2* z, float2 w1) {
    float2 w[7];
    make_tw7(w1, w);
    twiddle_apply(z, w);
}

__device__ __forceinline__ float2 twf(float invden, int j) {
    float s, c;
    sincospif(-(float)j * invden, &s, &c);
    return make_float2(c, s);
}
__device__ __forceinline__ float2 twfc(float invden, int j) {   // conj
    float s, c;
    sincospif((float)j * invden, &s, &c);
    return make_float2(c, s);
}

__device__ __forceinline__ float2 shflx(float2 v, int m) {
    return make_float2(__shfl_xor_sync(0xffffffffu, v.x, m),
                       __shfl_xor_sync(0xffffffffu, v.y, m));
}

// distributed 4-pt DFT across lanes l=j2 (lane&3)
__device__ __forceinline__ void fwd4sh(float2* z, int l) {
#pragma unroll
    for (int p = 0; p < 8; p++) {
        float2 v = z[p];
        float2 q = shflx(v, 2);
        v = (l & 2) ? csub(q, v) : cadd(v, q);
        if (l == 3) v = cnegi(v);
        q = shflx(v, 1);
        v = (l & 1) ? csub(q, v) : cadd(v, q);
        z[p] = v;
    }
}

__device__ __forceinline__ void inv4sh(float2* z, int l) {
#pragma unroll
    for (int p = 0; p < 8; p++) {
        float2 v = z[p];
        float2 q = shflx(v, 1);
        v = (l & 1) ? csub(q, v) : cadd(v, q);
        if (l == 3) v = cposi(v);
        q = shflx(v, 2);
        v = (l & 2) ? csub(q, v) : cadd(v, q);
        z[p] = v;
    }
}

// ---- forward 2048-pt path (8-8-8-4), float2 exchanges, spectrum left in z ----
__device__ __forceinline__ void fft2048_fwd_reg(float2* z, float2* sX1, float2* sX2, int t) {
    const int binOf[8] = {0, 4, 1, 5, 2, 6, 3, 7};
    fwd8(z);
    twiddle_chain(z, twf(1.0f / 1024.0f, t));          // W_2048^t
#pragma unroll
    for (int p = 0; p < 8; p++) sX1[binOf[p] * 256 + t] = z[p];
    __syncthreads();

    int mA = t >> 5, j1 = t & 31;
#pragma unroll
    for (int v = 0; v < 8; v++) z[v] = sX1[mA * 256 + j1 + 32 * v];
    fwd8(z);
    twiddle_chain(z, twf(1.0f / 128.0f, j1));          // W_256^j1
#pragma unroll
    for (int p = 0; p < 8; p++) sX2[(mA * 8 + binOf[p]) * 36 + j1] = z[p];
    __syncthreads();

    int g = t >> 2, j2 = t & 3;
#pragma unroll
    for (int w = 0; w < 8; w++) z[w] = sX2[g * 36 + j2 + 4 * w];
    fwd8(z);
    twiddle_chain(z, twf(1.0f / 16.0f, j2));           // W_32^j2
    fwd4sh(z, j2);
}

// masked last-stage eval: |c|^2 at lags u=0,1,7 (+2 for t<=1, +6 for t>=1)
__device__ __forceinline__ float final_eval(const float2* Y, const float2* w, int t) {
    float2 y0  = Y[t];
    float2 y1  = cmul(Y[256 + t],  w[0]);
    float2 y2v = cmul(Y[512 + t],  w[1]);
    float2 y3  = cmul(Y[768 + t],  w[2]);
    float2 y4  = cmul(Y[1024 + t], w[3]);
    float2 y5  = cmul(Y[1280 + t], w[4]);
    float2 y6v = cmul(Y[1536 + t], w[5]);
    float2 y7  = cmul(Y[1792 + t], w[6]);
    const float r = 0.70710678118654752f;
    float2 P04 = cadd(y0, y4),   M04 = csub(y0, y4);
    float2 P26 = cadd(y2v, y6v), M26 = csub(y2v, y6v);
    float2 T1  = cadd(y1, y5),   S1  = csub(y1, y5);
    float2 T3  = cadd(y3, y7),   S3  = csub(y3, y7);
    float2 x0 = cadd(cadd(P04, P26), cadd(T1, T3));
    float2 sm = csub(S1, S3), sp = cadd(S1, S3);
    float2 a = make_float2(M04.x + r * sm.x, M04.y + r * sm.y);
    float2 b = make_float2(M26.x + r * sp.x, M26.y + r * sp.y);
    float lsum = x0.x * x0.x + x0.y * x0.y
               + 2.0f * (a.x * a.x + a.y * a.y + b.x * b.x + b.y * b.y);
    float2 e = csub(P04, P26);
    float2 f = csub(T1, T3);
    if (t == 0) {
        float2 x2 = make_float2(e.x - f.y, e.y + f.x);
        lsum += x2.x * x2.x + x2.y * x2.y;
    } else if (t == 1) {
        lsum += 2.0f * (e.x * e.x + e.y * e.y + f.x * f.x + f.y * f.y);
    } else {
        float2 x6 = make_float2(e.x + f.y, e.y - f.x);
        lsum += x6.x * x6.x + x6.y * x6.y;
    }
    return lsum;
}

// ---------------- alpha tables: variant 0 -> g_B (conj input), 1 -> g_B2 (plain) ----------------
__global__ __launch_bounds__(256) void alphafft_kernel(const float* __restrict__ ar,
                                                       const float* __restrict__ ai) {
    __shared__ float2 sX1[2048];
    __shared__ float2 sX2[2304];
    int q = blockIdx.x >> 1, var = blockIdx.x & 1, t = threadIdx.x;
    if (blockIdx.x == 0 && t == 0) g_acc = 0.0;

    float sgn = var ? 1.0f : -1.0f;
    float2 z[8];
#pragma unroll
    for (int u = 0; u < 8; u++) {
        int i = t + 256 * u;
        if (u <= 2 || (u == 3 && t < 255))
            z[u] = make_float2(ar[q * KW + i], sgn * ai[q * KW + i]);
        else
            z[u] = make_float2(0.f, 0.f);
    }
    fft2048_fwd_reg(z, sX1, sX2, t);

    float2* __restrict__ out = (var ? g_B2 : g_B) + q * LFFT + t * 8;
#pragma unroll
    for (int p = 0; p < 8; p++)
        out[p] = make_float2(z[p].x, -z[p].y);   // conj
}

// ---------------- G[n,f] and G2[n,f] for n = 0..263 ----------------
#define GN_PER 8
__global__ __launch_bounds__(128) void gcomb_kernel() {
    int f  = blockIdx.x * 128 + threadIdx.x;
    int n0 = blockIdx.y * GN_PER;
    float2 Bq[7], Cq[7], p[7], st[7];
#pragma unroll
    for (int q = 0; q < 7; q++) {
        Bq[q] = g_B [q * LFFT + f];
        Cq[q] = g_B2[q * LFFT + f];
        float qq = (float)(q - 3);
        float s, c;
        sincospif((float)n0 * qq * (1.0f / 256.0f), &s, &c);
        p[q] = make_float2(c, s);
        sincospif(qq * (1.0f / 256.0f), &s, &c);
        st[q] = make_float2(c, s);
    }
    float2* __restrict__ outG  = &g_G [n0 * LFFT + f];
    float2* __restrict__ outG2 = &g_G2[n0 * LFFT + f];
    const float inv = 1.0f / (float)LFFT;
#pragma unroll
    for (int n = 0; n < GN_PER; n++) {
        float gr = 0.f, gi = 0.f, hr = 0.f, hi = 0.f;
#pragma unroll
        for (int q = 0; q < 7; q++) {
            gr += p[q].x * Bq[q].x - p[q].y * Bq[q].y;
            gi += p[q].x * Bq[q].y + p[q].y * Bq[q].x;
            hr += p[q].x * Cq[q].x - p[q].y * Cq[q].y;
            hi += p[q].x * Cq[q].y + p[q].y * Cq[q].x;
        }
        outG [(size_t)n * LFFT] = make_float2(gr * inv, gi * inv);
        outG2[(size_t)n * LFFT] = make_float2(hr * inv, hi * inv);
#pragma unroll
        for (int q = 0; q < 7; q++) p[q] = cmul(p[q], st[q]);
    }
}

// ---------------- STFT: register radix-8, 4 packed FFTs (8 frames) per 256-thread block ----------------
#define WSPAN4 (7 * HOPSZ + NFFT)   // 1408
#define SST    584
__global__ __launch_bounds__(256) void stft_kernel(const float* __restrict__ wav,
                                                   const float* __restrict__ win) {
    __shared__ float sRe[4 * SST];
    __shared__ float sIm[4 * SST];
    __shared__ float sWav[WSPAN4];
    __shared__ float sWin[NFFT];

    int hc  = blockIdx.x;              // half-chunk 0..129
    int b   = blockIdx.y;
    int tid = threadIdx.x;             // 256
    int tf0 = hc * 8;
    int f   = tid >> 6;
    int j   = tid & 63;

    for (int i = tid; i < NFFT; i += 256) sWin[i] = win[i];
    {
        int base = tf0 * HOPSZ - 256;
        const float* __restrict__ wb = wav + b * LSAMP;
#pragma unroll
        for (int k = 0; k < 6; k++) {
            int i = tid + k * 256;
            if (i < WSPAN4) {
                int p = base + i;
                if (p < 0) p = -p;
                if (p >= LSAMP) p = 2 * LSAMP - 2 - p;
                sWav[i] = wb[p];
            }
        }
    }
    __syncthreads();

    float* fRe = &sRe[f * SST];
    float* fIm = &sIm[f * SST];
    float2 z[8];
    const int binOf[8] = {0, 4, 1, 5, 2, 6, 3, 7};

#pragma unroll
    for (int u = 0; u < 8; u++) {
        int i = j + 64 * u;
        float wv = sWin[i];
        z[u] = make_float2(sWav[256 * f + i] * wv, sWav[256 * f + 128 + i] * wv);
    }
    fwd8(z);
    twiddle_chain(z, twf(1.0f / 256.0f, j));           // W_512^j
#pragma unroll
    for (int p = 0; p < 8; p++) {
        fRe[binOf[p] * 72 + j] = z[p].x;
        fIm[binOf[p] * 72 + j] = z[p].y;
    }
    __syncthreads();

    {
        int m = j >> 3, j0 = j & 7;
#pragma unroll
        for (int u = 0; u < 8; u++) {
            int a = m * 72 + j0 + 8 * u;
            z[u] = make_float2(fRe[a], fIm[a]);
        }
        fwd8(z);
        twiddle_chain(z, twf(1.0f / 32.0f, j0));       // W_64^j0
        __syncthreads();
#pragma unroll
        for (int p = 0; p < 8; p++) {
            int a = (m * 8 + binOf[p]) * 9 + j0;
            fRe[a] = z[p].x;
            fIm[a] = z[p].y;
        }
    }
    __syncthreads();

    {
#pragma unroll
        for (int u = 0; u < 8; u++) {
            int a = j * 9 + u;
            z[u] = make_float2(fRe[a], fIm[a]);
        }
        fwd8(z);
        __syncthreads();
        int m = j >> 3, mB = j & 7;
#pragma unroll
        for (int p = 0; p < 8; p++) {
            int n = m + 8 * mB + 64 * binOf[p];
            fRe[n] = z[p].x;
            fIm[n] = z[p].y;
        }
    }
    __syncthreads();

    int chunk = hc >> 1, off8 = (hc & 1) * 8;
#pragma unroll
    for (int k = 0; k < 8; k++) {
        int o = tid + k * 256;             // o = n*4 + p
        int n = o >> 2, p = o & 3;
        int m512 = (NFFT - n) & (NFFT - 1);
        float Znr = sRe[p * SST + n],    Zni = sIm[p * SST + n];
        float Zmr = sRe[p * SST + m512], Zmi = sIm[p * SST + m512];
        int te = tf0 + 2 * p;
        float4 hv;
        if (te <= 1024) {
            hv.x = 0.5f * (Znr + Zmr);  hv.y = 0.5f * (Zni - Zmi);
        } else { hv.x = 0.f; hv.y = 0.f; }
        if (te + 1 <= 1024) {
            hv.z = 0.5f * (Zni + Zmi);  hv.w = -0.5f * (Znr - Zmr);
        } else { hv.z = 0.f; hv.w = 0.f; }
        float4* __restrict__ dst =
            (float4*)&g_Ht[(((size_t)chunk * NROWS + b * NFFT + n) << 4) + off8 + 2 * p];
        *dst = hv;
    }
}

// ---------------- conv: conjugate-pair rows, interleaved dual inverse, fused finalize ----------------
#define CONV_BLOCKS (257 * BATCH)
__global__ __launch_bounds__(256, 4) void conv_kernel(float* __restrict__ out) {
    // pool regions (float2):
    //   sA  = [0,2048)      fwd stage-A / spectrum stash S / Y1
    //   sB  = [2048,4352)   fwd stage-B = inv X1 (self-addressed) / Y2 at [2048,4096)
    //   X2  = [4352,6656)   inv z2 C' output
    __shared__ float2 pool[6656];
    __shared__ float warpsum[8];
    float2* sA = pool;
    float2* sB = pool + 2048;
    float2* X2 = pool + 4352;

    int n   = blockIdx.x;              // 0..256
    int b   = blockIdx.y;
    int row = b * NFFT + n;
    int t   = threadIdx.x;
    bool dual = (n != 0) && (n != 256);

    const int posOf[8] = {0, 2, 4, 6, 1, 3, 5, 7};
    int g  = t >> 2, j2 = t & 3;
    int mA = t >> 5, j1 = t & 31;

    float2 z[8];
#pragma unroll
    for (int u = 0; u < 4; u++) {
        int i = t + 256 * u;
        z[u] = g_Ht[(((i >> 4) * NROWS + row) << 4) + (i & 15)];
    }
    z[4] = (t == 0) ? g_Ht[((64 * NROWS + row) << 4)] : make_float2(0.f, 0.f);
    z[5] = make_float2(0.f, 0.f);
    z[6] = make_float2(0.f, 0.f);
    z[7] = make_float2(0.f, 0.f);

    fft2048_fwd_reg(z, sA, sB, t);     // spectrum in z; sA dead, sB holds fwd-C data (self-addr)

    // stash spectrum into sA (conflict-free p*256+t)
    if (dual) {
#pragma unroll
        for (int p = 0; p < 8; p++) sA[p * 256 + t] = z[p];
    }

    // shared C' twiddle tree
    float2 wC[7];
    make_tw7(twfc(1.0f / 16.0f, j2), wC);

    // z1 = X*G, inverse C' -> X1 (= sB region, same per-thread addresses as fwd-C reads)
    {
        const float4* __restrict__ Gr = (const float4*)&g_G[(size_t)n * LFFT + t * 8];
#pragma unroll
        for (int cc = 0; cc < 4; cc++) {
            float4 gg = Gr[cc];
            float2 x0 = z[2 * cc], x1 = z[2 * cc + 1];
            z[2 * cc]     = make_float2(x0.x * gg.x - x0.y * gg.y, x0.x * gg.y + x0.y * gg.x);
            z[2 * cc + 1] = make_float2(x1.x * gg.z - x1.y * gg.w, x1.x * gg.w + x1.y * gg.z);
        }
    }
    inv4sh(z, j2);
    twiddle_apply(z, wC);
    inv8(z);
#pragma unroll
    for (int w = 0; w < 8; w++) sB[g * 36 + j2 + 4 * w] = z[w];

    // z2 = X*G2, inverse C' -> X2 (virgin region)
    if (dual) {
#pragma unroll
        for (int p = 0; p < 8; p++) z[p] = sA[p * 256 + t];
        const float4* __restrict__ G2r = (const float4*)&g_G2[(size_t)n * LFFT + t * 8];
#pragma unroll
        for (int cc = 0; cc < 4; cc++) {
            float4 gg = G2r[cc];
            float2 x0 = z[2 * cc], x1 = z[2 * cc + 1];
            z[2 * cc]     = make_float2(x0.x * gg.x - x0.y * gg.y, x0.x * gg.y + x0.y * gg.x);
            z[2 * cc + 1] = make_float2(x1.x * gg.z - x1.y * gg.w, x1.x * gg.w + x1.y * gg.z);
        }
        inv4sh(z, j2);
        twiddle_apply(z, wC);
        inv8(z);
#pragma unroll
        for (int w = 0; w < 8; w++) X2[g * 36 + j2 + 4 * w] = z[w];
    }
    __syncthreads();

    // shared B' twiddle tree (alive across midbar)
    float2 wB[7];
    make_tw7(twfc(1.0f / 128.0f, j1), wB);

    // B' for z1: X1 -> Y1 (= sA region; disjoint from X1/X2 reads)
#pragma unroll
    for (int mB = 0; mB < 8; mB++)
        z[posOf[mB]] = sB[(mA * 8 + mB) * 36 + j1];
    twiddle_apply(z, wB);
    inv8(z);
#pragma unroll
    for (int v = 0; v < 8; v++) sA[mA * 256 + j1 + 32 * v] = z[v];
    __syncthreads();   // all X1 reads done -> sB region reusable as Y2

    // B' for z2: X2 -> Y2 (= sB[0,2048) region)
    if (dual) {
#pragma unroll
        for (int mB = 0; mB < 8; mB++)
            z[posOf[mB]] = X2[(mA * 8 + mB) * 36 + j1];
        twiddle_apply(z, wB);
        inv8(z);
#pragma unroll
        for (int v = 0; v < 8; v++) sB[mA * 256 + j1 + 32 * v] = z[v];
    }
    __syncthreads();

    // final masked eval, shared twiddle tree
    float2 wF[7];
    make_tw7(twfc(1.0f / 1024.0f, t), wF);
    float lsum = final_eval(sA, wF, t);
    if (dual) lsum += final_eval(sB, wF, t);

#pragma unroll
    for (int off = 16; off > 0; off >>= 1)
        lsum += __shfl_down_sync(0xffffffff, lsum, off);
    if ((t & 31) == 0) warpsum[t >> 5] = lsum;
    __syncthreads();
    if (t == 0) {
        float s = 0.f;
#pragma unroll
        for (int w = 0; w < 8; w++) s += warpsum[w];
        atomicAdd(&g_acc, (double)s);
        __threadfence();
        unsigned old = atomicAdd(&g_ticket, 1u);
        if (old == (unsigned)(CONV_BLOCKS - 1)) {
            double v = atomicAdd(&g_acc, 0.0);
            out[0] = (float)(v / (double)(BATCH * TFRAMES));
            g_ticket = 0;                 // reset for next graph replay
        }
    }
}

extern "C" void kernel_launch(void* const* d_in, const int* in_sizes, int n_in,
                              void* d_out, int out_size) {
    const float* wav = (const float*)d_in[0];
    const float* win = (const float*)d_in[1];
    const float* ar  = (const float*)d_in[2];
    const float* ai  = (const float*)d_in[3];

    alphafft_kernel<<<14, 256>>>(ar, ai);
    dim3 gG(LFFT / 128, 33);                 // n = 0..263 (covers 0..256 needed)
    gcomb_kernel<<<gG, 128>>>();
    dim3 gs(2 * NCHUNK, BATCH);
    stft_kernel<<<gs, 256>>>(wav, win);
    dim3 gc(257, BATCH);
    conv_kernel<<<gc, 256>>>((float*)d_out);
}